// round 9
// baseline (speedup 1.0000x reference)
#include <cuda_runtime.h>
#include <math.h>

#define NTOK 1024
#define CQ   768
#define CZ   128
#define NH   16
#define HD   48

// ---------------- scratch (static device memory) ----------------
__device__ float g_an  [NTOK * CQ];
__device__ float g_q   [NTOK * CQ];
__device__ float g_k   [NTOK * CQ];
__device__ float g_v   [NTOK * CQ];
__device__ float g_gate[NTOK * CQ];
__device__ float g_og  [NTOK * CQ];
__device__ float g_sc  [(size_t)NTOK * NH * NTOK];   // pair+mask bias, layout [i][h][j]
__device__ float g_wp  [CZ * NH];
__device__ float g_wpT [NH * 132];                   // tf32(gz*wz) transposed [h][c]
__device__ float g_Wh  [NH];
__device__ float g_ch  [NH];

// ---------------- tf32 helpers ----------------
__device__ __forceinline__ unsigned f2tf(float x) {
    unsigned u; asm("cvt.rna.tf32.f32 %0, %1;" : "=r"(u) : "f"(x)); return u;
}
__device__ __forceinline__ float tf32f(float x) { return __uint_as_float(f2tf(x)); }
__device__ __forceinline__ unsigned su(float x) { return __float_as_uint(x); }

#define MMA_TF32(c, a, b0_, b1_)                                              \
    asm volatile("mma.sync.aligned.m16n8k8.row.col.f32.tf32.tf32.f32 "        \
                 "{%0,%1,%2,%3}, {%4,%5,%6,%7}, {%8,%9}, {%0,%1,%2,%3};"      \
                 : "+f"(c[0]), "+f"(c[1]), "+f"(c[2]), "+f"(c[3])             \
                 : "r"(a[0]), "r"(a[1]), "r"(a[2]), "r"(a[3]),                \
                   "r"(b0_), "r"(b1_));

// ---------------- LayerNorm of a ----------------
__global__ void __launch_bounds__(256) ln_a_kernel(const float* __restrict__ a,
                                                   const float* __restrict__ gw,
                                                   const float* __restrict__ bw) {
    int row = blockIdx.x;
    int tid = threadIdx.x;
    const float* x = a + (size_t)row * CQ;
    __shared__ float red[256];

    float xv[3];
    float s = 0.f;
#pragma unroll
    for (int k = 0; k < 3; k++) { xv[k] = x[tid + k * 256]; s += xv[k]; }
    red[tid] = s; __syncthreads();
    for (int st = 128; st > 0; st >>= 1) { if (tid < st) red[tid] += red[tid + st]; __syncthreads(); }
    float mu = red[0] * (1.f / CQ);
    __syncthreads();

    float s2 = 0.f;
#pragma unroll
    for (int k = 0; k < 3; k++) { float d = xv[k] - mu; s2 += d * d; }
    red[tid] = s2; __syncthreads();
    for (int st = 128; st > 0; st >>= 1) { if (tid < st) red[tid] += red[tid + st]; __syncthreads(); }
    float rs = rsqrtf(red[0] * (1.f / CQ) + 1e-5f);

#pragma unroll
    for (int k = 0; k < 3; k++) {
        int i = tid + k * 256;
        g_an[(size_t)row * CQ + i] = (xv[k] - mu) * rs * gw[i] + bw[i];
    }
}

// ---------------- pair-bias precompute ----------------
__global__ void prep_kernel(const float* __restrict__ gz,
                            const float* __restrict__ bz,
                            const float* __restrict__ wz) {
    int tid = threadIdx.x;       // 128
    float gzc = gz[tid];
    for (int h = 0; h < NH; h++) {
        float w = gzc * wz[tid * NH + h];
        g_wp[tid * NH + h] = w;
        g_wpT[h * 132 + tid] = tf32f(w);
    }
    __syncthreads();
    if (tid < NH) {
        float W = 0.f, C = 0.f;
        for (int c = 0; c < CZ; c++) {
            W += g_wp[c * NH + tid];
            C += bz[c] * wz[c * NH + tid];
        }
        g_Wh[tid] = W;
        g_ch[tid] = C;
    }
}

// ---------------- pair bias via tensor cores ----------------
__global__ void __launch_bounds__(256) pair_mma(const float* __restrict__ z,
                                                const float* __restrict__ mask) {
    extern __shared__ float psm[];
    float* zs  = psm;                     // 128*132
    float* wpt = zs + 128 * 132;          // 16*132
    float* sb  = wpt + 16 * 132;          // 16*132
    float* mus = sb + 16 * 132;           // 128
    float* rss = mus + 128;               // 128

    int i  = blockIdx.y;
    int j0 = blockIdx.x * 128;
    int tid = threadIdx.x, lane = tid & 31, w = tid >> 5;
    int g = lane >> 2, t = lane & 3;

    for (int e = tid; e < NH * 132; e += 256) wpt[e] = g_wpT[e];

    int row = tid >> 1, c0 = (tid & 1) * 64;
    const float* zrow = z + ((size_t)i * NTOK + j0 + row) * CZ + c0;
    float s1 = 0.f, s2 = 0.f;
#pragma unroll
    for (int q = 0; q < 16; q++) {
        float4 v = *(const float4*)&zrow[q * 4];
        s1 += v.x + v.y + v.z + v.w;
        s2 += v.x * v.x + v.y * v.y + v.z * v.z + v.w * v.w;
        float4 hv = make_float4(tf32f(v.x), tf32f(v.y), tf32f(v.z), tf32f(v.w));
        *(float4*)&zs[row * 132 + c0 + q * 4] = hv;
    }
    s1 += __shfl_xor_sync(0xffffffffu, s1, 1);
    s2 += __shfl_xor_sync(0xffffffffu, s2, 1);
    float mu = s1 * (1.f / CZ);
    float var = s2 * (1.f / CZ) - mu * mu;
    float rs = rsqrtf(var + 1e-5f);
    if ((tid & 1) == 0) { mus[row] = mu; rss[row] = rs; }
    __syncthreads();

    int wr = w * 16;
    float c[2][4] = {};
#pragma unroll
    for (int ks = 0; ks < 16; ks++) {
        int kk = ks * 8;
        unsigned a[4];
        a[0] = su(zs[(wr + g) * 132 + kk + t]);
        a[1] = su(zs[(wr + g + 8) * 132 + kk + t]);
        a[2] = su(zs[(wr + g) * 132 + kk + t + 4]);
        a[3] = su(zs[(wr + g + 8) * 132 + kk + t + 4]);
#pragma unroll
        for (int nt = 0; nt < 2; nt++) {
            unsigned b0 = su(wpt[(nt * 8 + g) * 132 + kk + t]);
            unsigned b1 = su(wpt[(nt * 8 + g) * 132 + kk + t + 4]);
            MMA_TF32(c[nt], a, b0, b1);
        }
    }

    float muA = mus[wr + g], rsA = rss[wr + g];
    float muB = mus[wr + g + 8], rsB = rss[wr + g + 8];
#pragma unroll
    for (int nt = 0; nt < 2; nt++) {
#pragma unroll
        for (int cc = 0; cc < 2; cc++) {
            int h = nt * 8 + 2 * t + cc;
            float W = g_Wh[h], C0 = g_ch[h];
            sb[h * 132 + wr + g]     = rsA * (c[nt][cc]     - muA * W) + C0;
            sb[h * 132 + wr + g + 8] = rsB * (c[nt][cc + 2] - muB * W) + C0;
        }
    }
    __syncthreads();

    float mi = mask[i];
#pragma unroll
    for (int e = tid; e < NH * 128; e += 256) {
        int h = e >> 7, j = e & 127;
        float mb = 1.0e9f * (mi * mask[j0 + j] - 1.f);
        g_sc[((size_t)i * NH + h) * NTOK + j0 + j] = sb[h * 132 + j] + mb;
    }
}

// ================= 3xTF32 GEMM, interleaved hi/lo float2 smem, BK=16, 128x64 tile =================
// sA2: [16][132] float2 (cols 0..127 used, pad 4), sB2: [16][68] float2 (cols 0..63, pad 4)
__device__ __forceinline__ void gemm_core(const float* __restrict__ A,
                                          const float* __restrict__ B,
                                          float c[2][4][4],
                                          float2* sA2, float2* sB2) {
    int tid  = threadIdx.x;
    int lane = tid & 31, w = tid >> 5;
    int wm = w & 3, wn = w >> 2;
    int g = lane >> 2, t = lane & 3;
    int m0 = blockIdx.y * 128, n0 = blockIdx.x * 64;
    int arow = tid >> 1, akb = (tid & 1) * 8;
    int bk = tid >> 4, bn = (tid & 15) * 4;

    for (int k0 = 0; k0 < CQ; k0 += 16) {
        __syncthreads();
        {
            float4 v0 = *(const float4*)&A[(size_t)(m0 + arow) * CQ + k0 + akb];
            float4 v1 = *(const float4*)&A[(size_t)(m0 + arow) * CQ + k0 + akb + 4];
            float xs[8] = {v0.x, v0.y, v0.z, v0.w, v1.x, v1.y, v1.z, v1.w};
#pragma unroll
            for (int q = 0; q < 8; q++) {
                float hi = tf32f(xs[q]);
                sA2[(akb + q) * 132 + arow] = make_float2(hi, tf32f(xs[q] - hi));
            }
        }
        {
            float4 v = *(const float4*)&B[(size_t)(k0 + bk) * CQ + n0 + bn];
            float vs[4] = {v.x, v.y, v.z, v.w};
#pragma unroll
            for (int q = 0; q < 4; q++) {
                float hi = tf32f(vs[q]);
                sB2[bk * 68 + bn + q] = make_float2(hi, tf32f(vs[q] - hi));
            }
        }
        __syncthreads();

#pragma unroll
        for (int ks = 0; ks < 2; ks++) {
            int kk = ks * 8;
            unsigned Ah[2][4], Al[2][4], Bh[4][2], Bl[4][2];
#pragma unroll
            for (int mt = 0; mt < 2; mt++) {
                int mb = wm * 32 + mt * 16 + g;
                float2 p0 = sA2[(kk + t) * 132 + mb];
                float2 p1 = sA2[(kk + t) * 132 + mb + 8];
                float2 p2 = sA2[(kk + t + 4) * 132 + mb];
                float2 p3 = sA2[(kk + t + 4) * 132 + mb + 8];
                Ah[mt][0] = su(p0.x); Al[mt][0] = su(p0.y);
                Ah[mt][1] = su(p1.x); Al[mt][1] = su(p1.y);
                Ah[mt][2] = su(p2.x); Al[mt][2] = su(p2.y);
                Ah[mt][3] = su(p3.x); Al[mt][3] = su(p3.y);
            }
#pragma unroll
            for (int nt = 0; nt < 4; nt++) {
                int nb = wn * 32 + nt * 8 + g;
                float2 q0 = sB2[(kk + t) * 68 + nb];
                float2 q1 = sB2[(kk + t + 4) * 68 + nb];
                Bh[nt][0] = su(q0.x); Bl[nt][0] = su(q0.y);
                Bh[nt][1] = su(q1.x); Bl[nt][1] = su(q1.y);
            }
#pragma unroll
            for (int mt = 0; mt < 2; mt++)
#pragma unroll
                for (int nt = 0; nt < 4; nt++) {
                    MMA_TF32(c[mt][nt], Ah[mt], Bh[nt][0], Bh[nt][1]);
                    MMA_TF32(c[mt][nt], Ah[mt], Bl[nt][0], Bl[nt][1]);
                    MMA_TF32(c[mt][nt], Al[mt], Bh[nt][0], Bh[nt][1]);
                }
        }
    }
}

#define GEMM_SMEM                                                             \
    __shared__ float2 sA2[16 * 132];                                          \
    __shared__ float2 sB2[16 * 68];

// fused Q/K/V/Gate projections
__global__ void __launch_bounds__(256) qkvg_mma(const float* __restrict__ A,
                                                const float* __restrict__ wq,
                                                const float* __restrict__ wk,
                                                const float* __restrict__ wv,
                                                const float* __restrict__ wg,
                                                const float* __restrict__ bg,
                                                float qscale) {
    GEMM_SMEM
    int zi = blockIdx.z;
    const float* B = (zi == 0) ? wq : (zi == 1) ? wk : (zi == 2) ? wv : wg;
    float* O = (zi == 0) ? g_q : (zi == 1) ? g_k : (zi == 2) ? g_v : g_gate;

    float c[2][4][4] = {};
    gemm_core(A, B, c, sA2, sB2);

    int lane = threadIdx.x & 31, w = threadIdx.x >> 5;
    int wm = w & 3, wn = w >> 2;
    int g = lane >> 2, t = lane & 3;
    int m0 = blockIdx.y * 128, n0 = blockIdx.x * 64;
#pragma unroll
    for (int mt = 0; mt < 2; mt++) {
        int r0 = m0 + wm * 32 + mt * 16 + g;
#pragma unroll
        for (int nt = 0; nt < 4; nt++) {
            int col = n0 + wn * 32 + nt * 8 + 2 * t;
            float v0 = c[mt][nt][0], v1 = c[mt][nt][1];
            float v2 = c[mt][nt][2], v3 = c[mt][nt][3];
            if (zi == 0) { v0 *= qscale; v1 *= qscale; v2 *= qscale; v3 *= qscale; }
            if (zi == 3) {
                float2 bb = *(const float2*)&bg[col];
                v0 = 1.f / (1.f + __expf(-(v0 + bb.x)));
                v1 = 1.f / (1.f + __expf(-(v1 + bb.y)));
                v2 = 1.f / (1.f + __expf(-(v2 + bb.x)));
                v3 = 1.f / (1.f + __expf(-(v3 + bb.y)));
            }
            *(float2*)&O[(size_t)r0 * CQ + col]       = make_float2(v0, v1);
            *(float2*)&O[(size_t)(r0 + 8) * CQ + col] = make_float2(v2, v3);
        }
    }
}

// out projection
__global__ void __launch_bounds__(256) out_mma(const float* __restrict__ A,
                                               const float* __restrict__ B,
                                               float* __restrict__ C,
                                               const float* __restrict__ bias) {
    GEMM_SMEM
    float c[2][4][4] = {};
    gemm_core(A, B, c, sA2, sB2);

    int lane = threadIdx.x & 31, w = threadIdx.x >> 5;
    int wm = w & 3, wn = w >> 2;
    int g = lane >> 2, t = lane & 3;
    int m0 = blockIdx.y * 128, n0 = blockIdx.x * 64;
#pragma unroll
    for (int mt = 0; mt < 2; mt++) {
        int r0 = m0 + wm * 32 + mt * 16 + g;
#pragma unroll
        for (int nt = 0; nt < 4; nt++) {
            int col = n0 + wn * 32 + nt * 8 + 2 * t;
            float2 bb = *(const float2*)&bias[col];
            *(float2*)&C[(size_t)r0 * CQ + col] =
                make_float2(c[mt][nt][0] + bb.x, c[mt][nt][1] + bb.y);
            *(float2*)&C[(size_t)(r0 + 8) * CQ + col] =
                make_float2(c[mt][nt][2] + bb.x, c[mt][nt][3] + bb.y);
        }
    }
}

// ================= flash attention: 64 q-rows x 2 heads per block, 256 thr =================
// smem: Ks[2][64*68] | Vs[2][64*72] | Ps[8][16*68]
__global__ void __launch_bounds__(256) flash_mma() {
    extern __shared__ float fsm[];

    int tid = threadIdx.x, w = tid >> 5, lane = tid & 31;
    int hh = w >> 2, wl = w & 3;
    int g = lane >> 2, t = lane & 3;

    float* Ks = fsm + hh * 4352;
    float* Vs = fsm + 8704 + hh * 4608;
    float* Pw = fsm + 8704 + 9216 + w * 1088;

    int h  = blockIdx.y * 2 + hh;
    int i0 = blockIdx.x * 64;
    int irow = i0 + wl * 16 + g;

    unsigned aq[6][4];
    {
        const float* q0 = g_q + (size_t)irow * CQ + h * HD;
        const float* q8 = q0 + 8 * CQ;
#pragma unroll
        for (int ks = 0; ks < 6; ks++) {
            aq[ks][0] = f2tf(q0[ks * 8 + t]);
            aq[ks][1] = f2tf(q8[ks * 8 + t]);
            aq[ks][2] = f2tf(q0[ks * 8 + t + 4]);
            aq[ks][3] = f2tf(q8[ks * 8 + t + 4]);
        }
    }

    float o[6][4] = {};
    float mrunA = -1e30f, mrunB = -1e30f, lA = 0.f, lB = 0.f;

    for (int jt = 0; jt < 16; jt++) {
        int j0 = jt * 64;
        __syncthreads();
        // load K/V for both heads (tf32-rounded)
#pragma unroll
        for (int e = tid; e < 1536; e += 256) {
            int hd2 = (e >= 768);
            int e2 = e - hd2 * 768;
            int r = e2 / 12, cc = (e2 % 12) * 4;
            int hl = blockIdx.y * 2 + hd2;
            float* Kd = fsm + hd2 * 4352;
            float* Vd = fsm + 8704 + hd2 * 4608;
            float4 kv = *(const float4*)&g_k[(size_t)(j0 + r) * CQ + hl * HD + cc];
            Kd[r * 68 + cc + 0] = tf32f(kv.x); Kd[r * 68 + cc + 1] = tf32f(kv.y);
            Kd[r * 68 + cc + 2] = tf32f(kv.z); Kd[r * 68 + cc + 3] = tf32f(kv.w);
            float4 vv = *(const float4*)&g_v[(size_t)(j0 + r) * CQ + hl * HD + cc];
            Vd[r * 72 + cc + 0] = tf32f(vv.x); Vd[r * 72 + cc + 1] = tf32f(vv.y);
            Vd[r * 72 + cc + 2] = tf32f(vv.z); Vd[r * 72 + cc + 3] = tf32f(vv.w);
        }
        // stage this warp's bias tile
        for (int e = lane; e < 256; e += 32) {
            int r = e >> 4, c4 = (e & 15) * 4;
            *(float4*)&Pw[r * 68 + c4] =
                *(const float4*)&g_sc[((size_t)(i0 + wl * 16 + r) * NH + h) * NTOK + j0 + c4];
        }
        __syncthreads();

        float s[8][4];
#pragma unroll
        for (int nt = 0; nt < 8; nt++) {
            float2 bA = *(const float2*)&Pw[g * 68 + nt * 8 + 2 * t];
            float2 bB = *(const float2*)&Pw[(g + 8) * 68 + nt * 8 + 2 * t];
            s[nt][0] = bA.x; s[nt][1] = bA.y; s[nt][2] = bB.x; s[nt][3] = bB.y;
        }
#pragma unroll
        for (int ks = 0; ks < 6; ks++) {
#pragma unroll
            for (int nt = 0; nt < 8; nt++) {
                unsigned b0 = su(Ks[(nt * 8 + g) * 68 + ks * 8 + t]);
                unsigned b1 = su(Ks[(nt * 8 + g) * 68 + ks * 8 + t + 4]);
                MMA_TF32(s[nt], aq[ks], b0, b1);
            }
        }

        float mA = -1e30f, mB = -1e30f;
#pragma unroll
        for (int nt = 0; nt < 8; nt++) {
            mA = fmaxf(mA, fmaxf(s[nt][0], s[nt][1]));
            mB = fmaxf(mB, fmaxf(s[nt][2], s[nt][3]));
        }
#pragma unroll
        for (int oo = 1; oo <= 2; oo <<= 1) {
            mA = fmaxf(mA, __shfl_xor_sync(0xffffffffu, mA, oo));
            mB = fmaxf(mB, __shfl_xor_sync(0xffffffffu, mB, oo));
        }
        float mnA = fmaxf(mrunA, mA), mnB = fmaxf(mrunB, mB);
        float alA = __expf(mrunA - mnA), alB = __expf(mrunB - mnB);
        mrunA = mnA; mrunB = mnB;

        float sumA = 0.f, sumB = 0.f;
#pragma unroll
        for (int nt = 0; nt < 8; nt++) {
            s[nt][0] = __expf(s[nt][0] - mnA); s[nt][1] = __expf(s[nt][1] - mnA);
            s[nt][2] = __expf(s[nt][2] - mnB); s[nt][3] = __expf(s[nt][3] - mnB);
            sumA += s[nt][0] + s[nt][1];
            sumB += s[nt][2] + s[nt][3];
        }
#pragma unroll
        for (int oo = 1; oo <= 2; oo <<= 1) {
            sumA += __shfl_xor_sync(0xffffffffu, sumA, oo);
            sumB += __shfl_xor_sync(0xffffffffu, sumB, oo);
        }
        lA = lA * alA + sumA;
        lB = lB * alB + sumB;
#pragma unroll
        for (int nd = 0; nd < 6; nd++) {
            o[nd][0] *= alA; o[nd][1] *= alA;
            o[nd][2] *= alB; o[nd][3] *= alB;
        }

#pragma unroll
        for (int nt = 0; nt < 8; nt++) {
            *(float2*)&Pw[g * 68 + nt * 8 + 2 * t]       = make_float2(tf32f(s[nt][0]), tf32f(s[nt][1]));
            *(float2*)&Pw[(g + 8) * 68 + nt * 8 + 2 * t] = make_float2(tf32f(s[nt][2]), tf32f(s[nt][3]));
        }
        __syncwarp();

#pragma unroll
        for (int ks = 0; ks < 8; ks++) {
            unsigned pa[4];
            pa[0] = su(Pw[g * 68 + ks * 8 + t]);
            pa[1] = su(Pw[(g + 8) * 68 + ks * 8 + t]);
            pa[2] = su(Pw[g * 68 + ks * 8 + t + 4]);
            pa[3] = su(Pw[(g + 8) * 68 + ks * 8 + t + 4]);
#pragma unroll
            for (int nd = 0; nd < 6; nd++) {
                unsigned b0 = su(Vs[(ks * 8 + t) * 72 + nd * 8 + g]);
                unsigned b1 = su(Vs[(ks * 8 + t + 4) * 72 + nd * 8 + g]);
                MMA_TF32(o[nd], pa, b0, b1);
            }
        }
    }

    float iA = 1.f / lA, iB = 1.f / lB;
#pragma unroll
    for (int nd = 0; nd < 6; nd++) {
        int col = h * HD + nd * 8 + 2 * t;
        size_t iAx = (size_t)irow * CQ + col;
        size_t iBx = (size_t)(irow + 8) * CQ + col;
        float2 ga = *(const float2*)&g_gate[iAx];
        float2 gb = *(const float2*)&g_gate[iBx];
        *(float2*)&g_og[iAx] = make_float2(o[nd][0] * iA * ga.x, o[nd][1] * iA * ga.y);
        *(float2*)&g_og[iBx] = make_float2(o[nd][2] * iB * gb.x, o[nd][3] * iB * gb.y);
    }
}

// ------------------------------- launch -------------------------------
#define PB_SMEM ((128 * 132 + 16 * 132 + 16 * 132 + 256) * 4)
#define FL_SMEM ((2 * 4352 + 2 * 4608 + 8 * 1088) * 4)

extern "C" void kernel_launch(void* const* d_in, const int* in_sizes, int n_in,
                              void* d_out, int out_size) {
    const float* a    = (const float*)d_in[0];
    const float* z    = (const float*)d_in[1];
    const float* mask = (const float*)d_in[2];
    const float* ga   = (const float*)d_in[3];
    const float* ba   = (const float*)d_in[4];
    const float* gz   = (const float*)d_in[5];
    const float* bz   = (const float*)d_in[6];
    const float* wz   = (const float*)d_in[7];
    const float* wq   = (const float*)d_in[8];
    const float* wk   = (const float*)d_in[9];
    const float* wv   = (const float*)d_in[10];
    const float* wg   = (const float*)d_in[11];
    const float* bg   = (const float*)d_in[12];
    const float* wo   = (const float*)d_in[13];
    const float* bo   = (const float*)d_in[14];
    float* out = (float*)d_out;

    float *p_an, *p_og;
    cudaGetSymbolAddress((void**)&p_an, g_an);
    cudaGetSymbolAddress((void**)&p_og, g_og);

    static cudaStream_t s1;
    static cudaEvent_t evFork, evJoin;
    static int init_done = 0;
    if (!init_done) {
        cudaFuncSetAttribute(flash_mma, cudaFuncAttributeMaxDynamicSharedMemorySize, FL_SMEM);
        cudaFuncSetAttribute(pair_mma,  cudaFuncAttributeMaxDynamicSharedMemorySize, PB_SMEM);
        cudaStreamCreateWithFlags(&s1, cudaStreamNonBlocking);
        cudaEventCreateWithFlags(&evFork, cudaEventDisableTiming);
        cudaEventCreateWithFlags(&evJoin, cudaEventDisableTiming);
        init_done = 1;
    }

    // fork: pair-bias path on side stream, projections on main stream
    cudaEventRecord(evFork, 0);
    cudaStreamWaitEvent(s1, evFork, 0);

    prep_kernel<<<1, 128, 0, s1>>>(gz, bz, wz);
    pair_mma<<<dim3(NTOK / 128, NTOK), 256, PB_SMEM, s1>>>(z, mask);
    cudaEventRecord(evJoin, s1);

    ln_a_kernel<<<NTOK, 256>>>(a, ga, ba);
    float qscale = 1.0f / sqrtf((float)HD);
    qkvg_mma<<<dim3(CQ / 64, NTOK / 128, 4), 256>>>(p_an, wq, wk, wv, wg, bg, qscale);

    // join
    cudaStreamWaitEvent(0, evJoin, 0);

    flash_mma<<<dim3(NTOK / 64, NH / 2), 256, FL_SMEM>>>();

    out_mma<<<dim3(CQ / 64, NTOK / 128), 256>>>(p_og, wo, out, bo);
}

// round 10
// speedup vs baseline: 1.3210x; 1.3210x over previous
#include <cuda_runtime.h>
#include <math.h>

#define NTOK 1024
#define CQ   768
#define CZ   128
#define NH   16
#define HD   48

// ---------------- scratch (static device memory) ----------------
__device__ float g_q   [NTOK * CQ];
__device__ float g_k   [NTOK * CQ];
__device__ float g_v   [NTOK * CQ];
__device__ float g_gate[NTOK * CQ];
__device__ float g_og  [NTOK * CQ];
__device__ float g_sc  [(size_t)NTOK * NH * NTOK];   // pair+mask bias, layout [i][h][j]
__device__ float g_wp  [CZ * NH];
__device__ float g_wpT [NH * 132];
__device__ float g_Wh  [NH];
__device__ float g_ch  [NH];
__device__ float g_mu  [NTOK];
__device__ float g_rs  [NTOK];

// ---------------- tf32 helpers ----------------
__device__ __forceinline__ unsigned f2tf(float x) {
    unsigned u; asm("cvt.rna.tf32.f32 %0, %1;" : "=r"(u) : "f"(x)); return u;
}
__device__ __forceinline__ float tf32f(float x) { return __uint_as_float(f2tf(x)); }
__device__ __forceinline__ unsigned su(float x) { return __float_as_uint(x); }

#define MMA_TF32(c, a, b0_, b1_)                                              \
    asm volatile("mma.sync.aligned.m16n8k8.row.col.f32.tf32.tf32.f32 "        \
                 "{%0,%1,%2,%3}, {%4,%5,%6,%7}, {%8,%9}, {%0,%1,%2,%3};"      \
                 : "+f"(c[0]), "+f"(c[1]), "+f"(c[2]), "+f"(c[3])             \
                 : "r"(a[0]), "r"(a[1]), "r"(a[2]), "r"(a[3]),                \
                   "r"(b0_), "r"(b1_));

// ---------------- per-row LN stats of a (mu, rs only) ----------------
__global__ void __launch_bounds__(256) a_stats_kernel(const float* __restrict__ a) {
    int row = blockIdx.x;
    int tid = threadIdx.x;
    const float* x = a + (size_t)row * CQ;
    __shared__ float red[256];

    float xv[3];
    float s = 0.f;
#pragma unroll
    for (int k = 0; k < 3; k++) { xv[k] = x[tid + k * 256]; s += xv[k]; }
    red[tid] = s; __syncthreads();
    for (int st = 128; st > 0; st >>= 1) { if (tid < st) red[tid] += red[tid + st]; __syncthreads(); }
    float mu = red[0] * (1.f / CQ);
    __syncthreads();

    float s2 = 0.f;
#pragma unroll
    for (int k = 0; k < 3; k++) { float d = xv[k] - mu; s2 += d * d; }
    red[tid] = s2; __syncthreads();
    for (int st = 128; st > 0; st >>= 1) { if (tid < st) red[tid] += red[tid + st]; __syncthreads(); }
    if (tid == 0) {
        g_mu[row] = mu;
        g_rs[row] = rsqrtf(red[0] * (1.f / CQ) + 1e-5f);
    }
}

// ---------------- pair-bias precompute ----------------
__global__ void prep_kernel(const float* __restrict__ gz,
                            const float* __restrict__ bz,
                            const float* __restrict__ wz) {
    int tid = threadIdx.x;       // 128
    float gzc = gz[tid];
    for (int h = 0; h < NH; h++) {
        float w = gzc * wz[tid * NH + h];
        g_wp[tid * NH + h] = w;
        g_wpT[h * 132 + tid] = tf32f(w);
    }
    __syncthreads();
    if (tid < NH) {
        float W = 0.f, C = 0.f;
        for (int c = 0; c < CZ; c++) {
            W += g_wp[c * NH + tid];
            C += bz[c] * wz[c * NH + tid];
        }
        g_Wh[tid] = W;
        g_ch[tid] = C;
    }
}

// ---------------- pair bias via tensor cores ----------------
__global__ void __launch_bounds__(256) pair_mma(const float* __restrict__ z,
                                                const float* __restrict__ mask) {
    extern __shared__ float psm[];
    float* zs  = psm;                     // 128*132
    float* wpt = zs + 128 * 132;          // 16*132
    float* sb  = wpt + 16 * 132;          // 16*132
    float* mus = sb + 16 * 132;           // 128
    float* rss = mus + 128;               // 128

    int i  = blockIdx.y;
    int j0 = blockIdx.x * 128;
    int tid = threadIdx.x, lane = tid & 31, w = tid >> 5;
    int g = lane >> 2, t = lane & 3;

    for (int e = tid; e < NH * 132; e += 256) wpt[e] = g_wpT[e];

    int row = tid >> 1, c0 = (tid & 1) * 64;
    const float* zrow = z + ((size_t)i * NTOK + j0 + row) * CZ + c0;
    float s1 = 0.f, s2 = 0.f;
#pragma unroll
    for (int q = 0; q < 16; q++) {
        float4 v = *(const float4*)&zrow[q * 4];
        s1 += v.x + v.y + v.z + v.w;
        s2 += v.x * v.x + v.y * v.y + v.z * v.z + v.w * v.w;
        float4 hv = make_float4(tf32f(v.x), tf32f(v.y), tf32f(v.z), tf32f(v.w));
        *(float4*)&zs[row * 132 + c0 + q * 4] = hv;
    }
    s1 += __shfl_xor_sync(0xffffffffu, s1, 1);
    s2 += __shfl_xor_sync(0xffffffffu, s2, 1);
    float mu = s1 * (1.f / CZ);
    float var = s2 * (1.f / CZ) - mu * mu;
    float rs = rsqrtf(var + 1e-5f);
    if ((tid & 1) == 0) { mus[row] = mu; rss[row] = rs; }
    __syncthreads();

    int wr = w * 16;
    float c[2][4] = {};
#pragma unroll
    for (int ks = 0; ks < 16; ks++) {
        int kk = ks * 8;
        unsigned a[4];
        a[0] = su(zs[(wr + g) * 132 + kk + t]);
        a[1] = su(zs[(wr + g + 8) * 132 + kk + t]);
        a[2] = su(zs[(wr + g) * 132 + kk + t + 4]);
        a[3] = su(zs[(wr + g + 8) * 132 + kk + t + 4]);
#pragma unroll
        for (int nt = 0; nt < 2; nt++) {
            unsigned b0 = su(wpt[(nt * 8 + g) * 132 + kk + t]);
            unsigned b1 = su(wpt[(nt * 8 + g) * 132 + kk + t + 4]);
            MMA_TF32(c[nt], a, b0, b1);
        }
    }

    float muA = mus[wr + g], rsA = rss[wr + g];
    float muB = mus[wr + g + 8], rsB = rss[wr + g + 8];
#pragma unroll
    for (int nt = 0; nt < 2; nt++) {
#pragma unroll
        for (int cc = 0; cc < 2; cc++) {
            int h = nt * 8 + 2 * t + cc;
            float W = g_Wh[h], C0 = g_ch[h];
            sb[h * 132 + wr + g]     = rsA * (c[nt][cc]     - muA * W) + C0;
            sb[h * 132 + wr + g + 8] = rsB * (c[nt][cc + 2] - muB * W) + C0;
        }
    }
    __syncthreads();

    float mi = mask[i];
#pragma unroll
    for (int e = tid; e < NH * 128; e += 256) {
        int h = e >> 7, j = e & 127;
        float mb = 1.0e9f * (mi * mask[j0 + j] - 1.f);
        g_sc[((size_t)i * NH + h) * NTOK + j0 + j] = sb[h * 132 + j] + mb;
    }
}

// ================= 3xTF32 GEMM 128x96 tile, BK=16, 256 thr, fused LN on A =================
// sAh/sAl: [16][136], sBh/sBl: [16][104]
// 8 warps: wm = w&3 (4 x 32 rows), wn = w>>2 (2 x 48 cols); per warp 2x6 mma tiles.
template <int LN_A>
__device__ __forceinline__ void gemm_core96(const float* __restrict__ A,
                                            const float* __restrict__ B,
                                            const float* __restrict__ gw,
                                            const float* __restrict__ bw,
                                            float c[2][6][4],
                                            float* sAh, float* sAl,
                                            float* sBh, float* sBl) {
    int tid  = threadIdx.x;
    int lane = tid & 31, w = tid >> 5;
    int wm = w & 3, wn = w >> 2;
    int g = lane >> 2, t = lane & 3;
    int m0 = blockIdx.y * 128, n0 = blockIdx.x * 96;
    int arow = tid >> 1, akb = (tid & 1) * 8;

    float mu = 0.f, rs = 1.f;
    if (LN_A) { mu = g_mu[m0 + arow]; rs = g_rs[m0 + arow]; }

    for (int k0 = 0; k0 < CQ; k0 += 16) {
        __syncthreads();
        {
            float4 v0 = *(const float4*)&A[(size_t)(m0 + arow) * CQ + k0 + akb];
            float4 v1 = *(const float4*)&A[(size_t)(m0 + arow) * CQ + k0 + akb + 4];
            float xs[8] = {v0.x, v0.y, v0.z, v0.w, v1.x, v1.y, v1.z, v1.w};
            if (LN_A) {
                float4 gg0 = *(const float4*)&gw[k0 + akb];
                float4 gg1 = *(const float4*)&gw[k0 + akb + 4];
                float4 bb0 = *(const float4*)&bw[k0 + akb];
                float4 bb1 = *(const float4*)&bw[k0 + akb + 4];
                float gs[8] = {gg0.x, gg0.y, gg0.z, gg0.w, gg1.x, gg1.y, gg1.z, gg1.w};
                float bs[8] = {bb0.x, bb0.y, bb0.z, bb0.w, bb1.x, bb1.y, bb1.z, bb1.w};
#pragma unroll
                for (int q = 0; q < 8; q++) xs[q] = (xs[q] - mu) * rs * gs[q] + bs[q];
            }
#pragma unroll
            for (int q = 0; q < 8; q++) {
                float hi = tf32f(xs[q]);
                sAh[(akb + q) * 136 + arow] = hi;
                sAl[(akb + q) * 136 + arow] = tf32f(xs[q] - hi);
            }
        }
        // B tile: 16 rows x 96 cols = 384 float4 loads over 256 threads
#pragma unroll
        for (int e = tid; e < 384; e += 256) {
            int brow = e / 24, bc = (e % 24) * 4;
            float4 v = *(const float4*)&B[(size_t)(k0 + brow) * CQ + n0 + bc];
            float vs[4] = {v.x, v.y, v.z, v.w};
#pragma unroll
            for (int q = 0; q < 4; q++) {
                float hi = tf32f(vs[q]);
                sBh[brow * 104 + bc + q] = hi;
                sBl[brow * 104 + bc + q] = tf32f(vs[q] - hi);
            }
        }
        __syncthreads();

#pragma unroll
        for (int ks = 0; ks < 2; ks++) {
            int kk = ks * 8;
            unsigned Ah[2][4], Al[2][4], Bh[6][2], Bl[6][2];
#pragma unroll
            for (int mt = 0; mt < 2; mt++) {
                int mb = wm * 32 + mt * 16 + g;
                Ah[mt][0] = su(sAh[(kk + t) * 136 + mb]);
                Ah[mt][1] = su(sAh[(kk + t) * 136 + mb + 8]);
                Ah[mt][2] = su(sAh[(kk + t + 4) * 136 + mb]);
                Ah[mt][3] = su(sAh[(kk + t + 4) * 136 + mb + 8]);
                Al[mt][0] = su(sAl[(kk + t) * 136 + mb]);
                Al[mt][1] = su(sAl[(kk + t) * 136 + mb + 8]);
                Al[mt][2] = su(sAl[(kk + t + 4) * 136 + mb]);
                Al[mt][3] = su(sAl[(kk + t + 4) * 136 + mb + 8]);
            }
#pragma unroll
            for (int nt = 0; nt < 6; nt++) {
                int nb = wn * 48 + nt * 8 + g;
                Bh[nt][0] = su(sBh[(kk + t) * 104 + nb]);
                Bh[nt][1] = su(sBh[(kk + t + 4) * 104 + nb]);
                Bl[nt][0] = su(sBl[(kk + t) * 104 + nb]);
                Bl[nt][1] = su(sBl[(kk + t + 4) * 104 + nb]);
            }
#pragma unroll
            for (int mt = 0; mt < 2; mt++)
#pragma unroll
                for (int nt = 0; nt < 6; nt++) {
                    MMA_TF32(c[mt][nt], Ah[mt], Bh[nt][0], Bh[nt][1]);
                    MMA_TF32(c[mt][nt], Ah[mt], Bl[nt][0], Bl[nt][1]);
                    MMA_TF32(c[mt][nt], Al[mt], Bh[nt][0], Bh[nt][1]);
                }
        }
    }
}

#define GEMM96_SMEM                                                           \
    __shared__ float sAh[16 * 136], sAl[16 * 136];                            \
    __shared__ float sBh[16 * 104], sBl[16 * 104];

// fused Q/K/V/Gate projections (LN applied to A on the fly)
__global__ void __launch_bounds__(256) qkvg_mma(const float* __restrict__ A,
                                                const float* __restrict__ gw,
                                                const float* __restrict__ bw,
                                                const float* __restrict__ wq,
                                                const float* __restrict__ wk,
                                                const float* __restrict__ wv,
                                                const float* __restrict__ wg,
                                                const float* __restrict__ bg,
                                                float qscale) {
    GEMM96_SMEM
    int zi = blockIdx.z;
    const float* B = (zi == 0) ? wq : (zi == 1) ? wk : (zi == 2) ? wv : wg;
    float* O = (zi == 0) ? g_q : (zi == 1) ? g_k : (zi == 2) ? g_v : g_gate;

    float c[2][6][4] = {};
    gemm_core96<1>(A, B, gw, bw, c, sAh, sAl, sBh, sBl);

    int lane = threadIdx.x & 31, w = threadIdx.x >> 5;
    int wm = w & 3, wn = w >> 2;
    int g = lane >> 2, t = lane & 3;
    int m0 = blockIdx.y * 128, n0 = blockIdx.x * 96;
#pragma unroll
    for (int mt = 0; mt < 2; mt++) {
        int r0 = m0 + wm * 32 + mt * 16 + g;
#pragma unroll
        for (int nt = 0; nt < 6; nt++) {
            int col = n0 + wn * 48 + nt * 8 + 2 * t;
            float v0 = c[mt][nt][0], v1 = c[mt][nt][1];
            float v2 = c[mt][nt][2], v3 = c[mt][nt][3];
            if (zi == 0) { v0 *= qscale; v1 *= qscale; v2 *= qscale; v3 *= qscale; }
            if (zi == 3) {
                float2 bb = *(const float2*)&bg[col];
                v0 = 1.f / (1.f + __expf(-(v0 + bb.x)));
                v1 = 1.f / (1.f + __expf(-(v1 + bb.y)));
                v2 = 1.f / (1.f + __expf(-(v2 + bb.x)));
                v3 = 1.f / (1.f + __expf(-(v3 + bb.y)));
            }
            *(float2*)&O[(size_t)r0 * CQ + col]       = make_float2(v0, v1);
            *(float2*)&O[(size_t)(r0 + 8) * CQ + col] = make_float2(v2, v3);
        }
    }
}

// out projection (no LN)
__global__ void __launch_bounds__(256) out_mma(const float* __restrict__ A,
                                               const float* __restrict__ B,
                                               float* __restrict__ C,
                                               const float* __restrict__ bias) {
    GEMM96_SMEM
    float c[2][6][4] = {};
    gemm_core96<0>(A, B, (const float*)0, (const float*)0, c, sAh, sAl, sBh, sBl);

    int lane = threadIdx.x & 31, w = threadIdx.x >> 5;
    int wm = w & 3, wn = w >> 2;
    int g = lane >> 2, t = lane & 3;
    int m0 = blockIdx.y * 128, n0 = blockIdx.x * 96;
#pragma unroll
    for (int mt = 0; mt < 2; mt++) {
        int r0 = m0 + wm * 32 + mt * 16 + g;
#pragma unroll
        for (int nt = 0; nt < 6; nt++) {
            int col = n0 + wn * 48 + nt * 8 + 2 * t;
            float2 bb = *(const float2*)&bias[col];
            *(float2*)&C[(size_t)r0 * CQ + col] =
                make_float2(c[mt][nt][0] + bb.x, c[mt][nt][1] + bb.y);
            *(float2*)&C[(size_t)(r0 + 8) * CQ + col] =
                make_float2(c[mt][nt][2] + bb.x, c[mt][nt][3] + bb.y);
        }
    }
}

// ================= flash attention: 64 q-rows x 2 heads per block, 256 thr =================
// smem: Ks[2][64*68] | Vs[2][64*72] | Ps[8][16*68]
__global__ void __launch_bounds__(256) flash_mma() {
    extern __shared__ float fsm[];

    int tid = threadIdx.x, w = tid >> 5, lane = tid & 31;
    int hh = w >> 2, wl = w & 3;
    int g = lane >> 2, t = lane & 3;

    float* Ks = fsm + hh * 4352;
    float* Vs = fsm + 8704 + hh * 4608;
    float* Pw = fsm + 8704 + 9216 + w * 1088;

    int h  = blockIdx.y * 2 + hh;
    int i0 = blockIdx.x * 64;
    int irow = i0 + wl * 16 + g;

    unsigned aq[6][4];
    {
        const float* q0 = g_q + (size_t)irow * CQ + h * HD;
        const float* q8 = q0 + 8 * CQ;
#pragma unroll
        for (int ks = 0; ks < 6; ks++) {
            aq[ks][0] = f2tf(q0[ks * 8 + t]);
            aq[ks][1] = f2tf(q8[ks * 8 + t]);
            aq[ks][2] = f2tf(q0[ks * 8 + t + 4]);
            aq[ks][3] = f2tf(q8[ks * 8 + t + 4]);
        }
    }

    float o[6][4] = {};
    float mrunA = -1e30f, mrunB = -1e30f, lA = 0.f, lB = 0.f;

    for (int jt = 0; jt < 16; jt++) {
        int j0 = jt * 64;
        __syncthreads();
#pragma unroll
        for (int e = tid; e < 1536; e += 256) {
            int hd2 = (e >= 768);
            int e2 = e - hd2 * 768;
            int r = e2 / 12, cc = (e2 % 12) * 4;
            int hl = blockIdx.y * 2 + hd2;
            float* Kd = fsm + hd2 * 4352;
            float* Vd = fsm + 8704 + hd2 * 4608;
            float4 kv = *(const float4*)&g_k[(size_t)(j0 + r) * CQ + hl * HD + cc];
            Kd[r * 68 + cc + 0] = tf32f(kv.x); Kd[r * 68 + cc + 1] = tf32f(kv.y);
            Kd[r * 68 + cc + 2] = tf32f(kv.z); Kd[r * 68 + cc + 3] = tf32f(kv.w);
            float4 vv = *(const float4*)&g_v[(size_t)(j0 + r) * CQ + hl * HD + cc];
            Vd[r * 72 + cc + 0] = tf32f(vv.x); Vd[r * 72 + cc + 1] = tf32f(vv.y);
            Vd[r * 72 + cc + 2] = tf32f(vv.z); Vd[r * 72 + cc + 3] = tf32f(vv.w);
        }
        for (int e = lane; e < 256; e += 32) {
            int r = e >> 4, c4 = (e & 15) * 4;
            *(float4*)&Pw[r * 68 + c4] =
                *(const float4*)&g_sc[((size_t)(i0 + wl * 16 + r) * NH + h) * NTOK + j0 + c4];
        }
        __syncthreads();

        float s[8][4];
#pragma unroll
        for (int nt = 0; nt < 8; nt++) {
            float2 bA = *(const float2*)&Pw[g * 68 + nt * 8 + 2 * t];
            float2 bB = *(const float2*)&Pw[(g + 8) * 68 + nt * 8 + 2 * t];
            s[nt][0] = bA.x; s[nt][1] = bA.y; s[nt][2] = bB.x; s[nt][3] = bB.y;
        }
#pragma unroll
        for (int ks = 0; ks < 6; ks++) {
#pragma unroll
            for (int nt = 0; nt < 8; nt++) {
                unsigned b0 = su(Ks[(nt * 8 + g) * 68 + ks * 8 + t]);
                unsigned b1 = su(Ks[(nt * 8 + g) * 68 + ks * 8 + t + 4]);
                MMA_TF32(s[nt], aq[ks], b0, b1);
            }
        }

        float mA = -1e30f, mB = -1e30f;
#pragma unroll
        for (int nt = 0; nt < 8; nt++) {
            mA = fmaxf(mA, fmaxf(s[nt][0], s[nt][1]));
            mB = fmaxf(mB, fmaxf(s[nt][2], s[nt][3]));
        }
#pragma unroll
        for (int oo = 1; oo <= 2; oo <<= 1) {
            mA = fmaxf(mA, __shfl_xor_sync(0xffffffffu, mA, oo));
            mB = fmaxf(mB, __shfl_xor_sync(0xffffffffu, mB, oo));
        }
        float mnA = fmaxf(mrunA, mA), mnB = fmaxf(mrunB, mB);
        float alA = __expf(mrunA - mnA), alB = __expf(mrunB - mnB);
        mrunA = mnA; mrunB = mnB;

        float sumA = 0.f, sumB = 0.f;
#pragma unroll
        for (int nt = 0; nt < 8; nt++) {
            s[nt][0] = __expf(s[nt][0] - mnA); s[nt][1] = __expf(s[nt][1] - mnA);
            s[nt][2] = __expf(s[nt][2] - mnB); s[nt][3] = __expf(s[nt][3] - mnB);
            sumA += s[nt][0] + s[nt][1];
            sumB += s[nt][2] + s[nt][3];
        }
#pragma unroll
        for (int oo = 1; oo <= 2; oo <<= 1) {
            sumA += __shfl_xor_sync(0xffffffffu, sumA, oo);
            sumB += __shfl_xor_sync(0xffffffffu, sumB, oo);
        }
        lA = lA * alA + sumA;
        lB = lB * alB + sumB;
#pragma unroll
        for (int nd = 0; nd < 6; nd++) {
            o[nd][0] *= alA; o[nd][1] *= alA;
            o[nd][2] *= alB; o[nd][3] *= alB;
        }

#pragma unroll
        for (int nt = 0; nt < 8; nt++) {
            *(float2*)&Pw[g * 68 + nt * 8 + 2 * t]       = make_float2(tf32f(s[nt][0]), tf32f(s[nt][1]));
            *(float2*)&Pw[(g + 8) * 68 + nt * 8 + 2 * t] = make_float2(tf32f(s[nt][2]), tf32f(s[nt][3]));
        }
        __syncwarp();

#pragma unroll
        for (int ks = 0; ks < 8; ks++) {
            unsigned pa[4];
            pa[0] = su(Pw[g * 68 + ks * 8 + t]);
            pa[1] = su(Pw[(g + 8) * 68 + ks * 8 + t]);
            pa[2] = su(Pw[g * 68 + ks * 8 + t + 4]);
            pa[3] = su(Pw[(g + 8) * 68 + ks * 8 + t + 4]);
#pragma unroll
            for (int nd = 0; nd < 6; nd++) {
                unsigned b0 = su(Vs[(ks * 8 + t) * 72 + nd * 8 + g]);
                unsigned b1 = su(Vs[(ks * 8 + t + 4) * 72 + nd * 8 + g]);
                MMA_TF32(o[nd], pa, b0, b1);
            }
        }
    }

    float iA = 1.f / lA, iB = 1.f / lB;
#pragma unroll
    for (int nd = 0; nd < 6; nd++) {
        int col = h * HD + nd * 8 + 2 * t;
        size_t iAx = (size_t)irow * CQ + col;
        size_t iBx = (size_t)(irow + 8) * CQ + col;
        float2 ga = *(const float2*)&g_gate[iAx];
        float2 gb = *(const float2*)&g_gate[iBx];
        *(float2*)&g_og[iAx] = make_float2(o[nd][0] * iA * ga.x, o[nd][1] * iA * ga.y);
        *(float2*)&g_og[iBx] = make_float2(o[nd][2] * iB * gb.x, o[nd][3] * iB * gb.y);
    }
}

// ------------------------------- launch -------------------------------
#define PB_SMEM ((128 * 132 + 16 * 132 + 16 * 132 + 256) * 4)
#define FL_SMEM ((2 * 4352 + 2 * 4608 + 8 * 1088) * 4)

extern "C" void kernel_launch(void* const* d_in, const int* in_sizes, int n_in,
                              void* d_out, int out_size) {
    const float* a    = (const float*)d_in[0];
    const float* z    = (const float*)d_in[1];
    const float* mask = (const float*)d_in[2];
    const float* ga   = (const float*)d_in[3];
    const float* ba   = (const float*)d_in[4];
    const float* gz   = (const float*)d_in[5];
    const float* bz   = (const float*)d_in[6];
    const float* wz   = (const float*)d_in[7];
    const float* wq   = (const float*)d_in[8];
    const float* wk   = (const float*)d_in[9];
    const float* wv   = (const float*)d_in[10];
    const float* wg   = (const float*)d_in[11];
    const float* bg   = (const float*)d_in[12];
    const float* wo   = (const float*)d_in[13];
    const float* bo   = (const float*)d_in[14];
    float* out = (float*)d_out;

    float *p_og;
    cudaGetSymbolAddress((void**)&p_og, g_og);

    static int init_done = 0;
    if (!init_done) {
        cudaFuncSetAttribute(flash_mma, cudaFuncAttributeMaxDynamicSharedMemorySize, FL_SMEM);
        cudaFuncSetAttribute(pair_mma,  cudaFuncAttributeMaxDynamicSharedMemorySize, PB_SMEM);
        init_done = 1;
    }

    a_stats_kernel<<<NTOK, 256>>>(a);
    prep_kernel<<<1, 128>>>(gz, bz, wz);
    pair_mma<<<dim3(NTOK / 128, NTOK), 256, PB_SMEM>>>(z, mask);

    float qscale = 1.0f / sqrtf((float)HD);
    qkvg_mma<<<dim3(CQ / 96, NTOK / 128, 4), 256>>>(a, ga, ba, wq, wk, wv, wg, bg, qscale);

    flash_mma<<<dim3(NTOK / 64, NH / 2), 256, FL_SMEM>>>();

    out_mma<<<dim3(CQ / 96, NTOK / 128), 256>>>(p_og, wo, out, bo);
}

// round 11
// speedup vs baseline: 1.5189x; 1.1498x over previous
#include <cuda_runtime.h>
#include <math.h>

#define NTOK 1024
#define CQ   768
#define CZ   128
#define NH   16
#define HD   48
#define NKCH (CQ / 16)   // 48 k-chunks

// ---------------- scratch (static device memory) ----------------
__device__ float g_q   [NTOK * CQ];
__device__ float g_k   [NTOK * CQ];
__device__ float g_v   [NTOK * CQ];
__device__ float g_gate[NTOK * CQ];
__device__ float g_og  [NTOK * CQ];
__device__ float g_sc  [(size_t)NTOK * NH * NTOK];   // pair+mask bias, layout [i][h][j]
__device__ float g_wp  [CZ * NH];
__device__ float g_wpT [NH * 132];
__device__ float g_Wh  [NH];
__device__ float g_ch  [NH];
__device__ float g_mu  [NTOK];
__device__ float g_rs  [NTOK];

// ---------------- tf32 helpers ----------------
__device__ __forceinline__ unsigned f2tf(float x) {
    unsigned u; asm("cvt.rna.tf32.f32 %0, %1;" : "=r"(u) : "f"(x)); return u;
}
__device__ __forceinline__ float tf32f(float x) { return __uint_as_float(f2tf(x)); }
__device__ __forceinline__ unsigned su(float x) { return __float_as_uint(x); }

#define MMA_TF32(c, a, b0_, b1_)                                              \
    asm volatile("mma.sync.aligned.m16n8k8.row.col.f32.tf32.tf32.f32 "        \
                 "{%0,%1,%2,%3}, {%4,%5,%6,%7}, {%8,%9}, {%0,%1,%2,%3};"      \
                 : "+f"(c[0]), "+f"(c[1]), "+f"(c[2]), "+f"(c[3])             \
                 : "r"(a[0]), "r"(a[1]), "r"(a[2]), "r"(a[3]),                \
                   "r"(b0_), "r"(b1_));

// ---------------- per-row LN stats of a ----------------
__global__ void __launch_bounds__(256) a_stats_kernel(const float* __restrict__ a) {
    int row = blockIdx.x;
    int tid = threadIdx.x;
    const float* x = a + (size_t)row * CQ;
    __shared__ float red[256];

    float xv[3];
    float s = 0.f;
#pragma unroll
    for (int k = 0; k < 3; k++) { xv[k] = x[tid + k * 256]; s += xv[k]; }
    red[tid] = s; __syncthreads();
    for (int st = 128; st > 0; st >>= 1) { if (tid < st) red[tid] += red[tid + st]; __syncthreads(); }
    float mu = red[0] * (1.f / CQ);
    __syncthreads();

    float s2 = 0.f;
#pragma unroll
    for (int k = 0; k < 3; k++) { float d = xv[k] - mu; s2 += d * d; }
    red[tid] = s2; __syncthreads();
    for (int st = 128; st > 0; st >>= 1) { if (tid < st) red[tid] += red[tid + st]; __syncthreads(); }
    if (tid == 0) {
        g_mu[row] = mu;
        g_rs[row] = rsqrtf(red[0] * (1.f / CQ) + 1e-5f);
    }
}

// ---------------- pair-bias precompute ----------------
__global__ void prep_kernel(const float* __restrict__ gz,
                            const float* __restrict__ bz,
                            const float* __restrict__ wz) {
    int tid = threadIdx.x;       // 128
    float gzc = gz[tid];
    for (int h = 0; h < NH; h++) {
        float w = gzc * wz[tid * NH + h];
        g_wp[tid * NH + h] = w;
        g_wpT[h * 132 + tid] = tf32f(w);
    }
    __syncthreads();
    if (tid < NH) {
        float W = 0.f, C = 0.f;
        for (int c = 0; c < CZ; c++) {
            W += g_wp[c * NH + tid];
            C += bz[c] * wz[c * NH + tid];
        }
        g_Wh[tid] = W;
        g_ch[tid] = C;
    }
}

// ---------------- pair bias via tensor cores (unchanged, proven) ----------------
__global__ void __launch_bounds__(256) pair_mma(const float* __restrict__ z,
                                                const float* __restrict__ mask) {
    extern __shared__ float psm[];
    float* zs  = psm;                     // 128*132
    float* wpt = zs + 128 * 132;          // 16*132
    float* sb  = wpt + 16 * 132;          // 16*132
    float* mus = sb + 16 * 132;           // 128
    float* rss = mus + 128;               // 128

    int i  = blockIdx.y;
    int j0 = blockIdx.x * 128;
    int tid = threadIdx.x, lane = tid & 31, w = tid >> 5;
    int g = lane >> 2, t = lane & 3;

    for (int e = tid; e < NH * 132; e += 256) wpt[e] = g_wpT[e];

    int row = tid >> 1, c0 = (tid & 1) * 64;
    const float* zrow = z + ((size_t)i * NTOK + j0 + row) * CZ + c0;
    float s1 = 0.f, s2 = 0.f;
#pragma unroll
    for (int q = 0; q < 16; q++) {
        float4 v = *(const float4*)&zrow[q * 4];
        s1 += v.x + v.y + v.z + v.w;
        s2 += v.x * v.x + v.y * v.y + v.z * v.z + v.w * v.w;
        float4 hv = make_float4(tf32f(v.x), tf32f(v.y), tf32f(v.z), tf32f(v.w));
        *(float4*)&zs[row * 132 + c0 + q * 4] = hv;
    }
    s1 += __shfl_xor_sync(0xffffffffu, s1, 1);
    s2 += __shfl_xor_sync(0xffffffffu, s2, 1);
    float mu = s1 * (1.f / CZ);
    float var = s2 * (1.f / CZ) - mu * mu;
    float rs = rsqrtf(var + 1e-5f);
    if ((tid & 1) == 0) { mus[row] = mu; rss[row] = rs; }
    __syncthreads();

    int wr = w * 16;
    float c[2][4] = {};
#pragma unroll
    for (int ks = 0; ks < 16; ks++) {
        int kk = ks * 8;
        unsigned a[4];
        a[0] = su(zs[(wr + g) * 132 + kk + t]);
        a[1] = su(zs[(wr + g + 8) * 132 + kk + t]);
        a[2] = su(zs[(wr + g) * 132 + kk + t + 4]);
        a[3] = su(zs[(wr + g + 8) * 132 + kk + t + 4]);
#pragma unroll
        for (int nt = 0; nt < 2; nt++) {
            unsigned b0 = su(wpt[(nt * 8 + g) * 132 + kk + t]);
            unsigned b1 = su(wpt[(nt * 8 + g) * 132 + kk + t + 4]);
            MMA_TF32(c[nt], a, b0, b1);
        }
    }

    float muA = mus[wr + g], rsA = rss[wr + g];
    float muB = mus[wr + g + 8], rsB = rss[wr + g + 8];
#pragma unroll
    for (int nt = 0; nt < 2; nt++) {
#pragma unroll
        for (int cc = 0; cc < 2; cc++) {
            int h = nt * 8 + 2 * t + cc;
            float W = g_Wh[h], C0 = g_ch[h];
            sb[h * 132 + wr + g]     = rsA * (c[nt][cc]     - muA * W) + C0;
            sb[h * 132 + wr + g + 8] = rsB * (c[nt][cc + 2] - muB * W) + C0;
        }
    }
    __syncthreads();

    float mi = mask[i];
#pragma unroll
    for (int e = tid; e < NH * 128; e += 256) {
        int h = e >> 7, j = e & 127;
        float mb = 1.0e9f * (mi * mask[j0 + j] - 1.f);
        g_sc[((size_t)i * NH + h) * NTOK + j0 + j] = sb[h * 132 + j] + mb;
    }
}

// ================= 3xTF32 GEMM, 128x64 tile, BK=16, double-buffered smem =================
// per buffer: sAh[16*136] sAl[16*136] sBh[16*72] sBl[16*72]  (6656 floats)
#define GSA (16 * 136)
#define GSB (16 * 72)
#define GBUF (2 * GSA + 2 * GSB)
#define GEMM_DB_SMEM (2 * GBUF * 4)

template <int LN_A>
__device__ __forceinline__ void gemm_core_db(const float* __restrict__ A,
                                             const float* __restrict__ B,
                                             const float* __restrict__ gw,
                                             const float* __restrict__ bw,
                                             float c[2][4][4], float* sm) {
    int tid  = threadIdx.x;
    int lane = tid & 31, w = tid >> 5;
    int wm = w & 3, wn = w >> 2;
    int g = lane >> 2, t = lane & 3;
    int m0 = blockIdx.y * 128, n0 = blockIdx.x * 64;
    int arow = tid >> 1, akb = (tid & 1) * 8;
    int bk = tid >> 4, bn = (tid & 15) * 4;

    float mu = 0.f, rs = 1.f;
    if (LN_A) { mu = g_mu[m0 + arow]; rs = g_rs[m0 + arow]; }

    const float* Arow = A + (size_t)(m0 + arow) * CQ;

    float pa[8], pb[4];
    // prologue: load k-chunk 0
    {
        float4 v0 = *(const float4*)&Arow[akb];
        float4 v1 = *(const float4*)&Arow[akb + 4];
        pa[0] = v0.x; pa[1] = v0.y; pa[2] = v0.z; pa[3] = v0.w;
        pa[4] = v1.x; pa[5] = v1.y; pa[6] = v1.z; pa[7] = v1.w;
        float4 vb = *(const float4*)&B[(size_t)bk * CQ + n0 + bn];
        pb[0] = vb.x; pb[1] = vb.y; pb[2] = vb.z; pb[3] = vb.w;
    }

#define STORE_BUF(bsel, k0)                                                   \
    {                                                                         \
        float* sAh_ = sm + (bsel) * GBUF;                                     \
        float* sAl_ = sAh_ + GSA;                                             \
        float* sBh_ = sAl_ + GSA;                                             \
        float* sBl_ = sBh_ + GSB;                                             \
        float xs[8];                                                          \
        _Pragma("unroll")                                                     \
        for (int q = 0; q < 8; q++) xs[q] = pa[q];                            \
        if (LN_A) {                                                           \
            _Pragma("unroll")                                                 \
            for (int q = 0; q < 8; q++)                                       \
                xs[q] = (xs[q] - mu) * rs * gw[(k0) + akb + q] + bw[(k0) + akb + q]; \
        }                                                                     \
        _Pragma("unroll")                                                     \
        for (int q = 0; q < 8; q++) {                                         \
            float hi = tf32f(xs[q]);                                          \
            sAh_[(akb + q) * 136 + arow] = hi;                                \
            sAl_[(akb + q) * 136 + arow] = tf32f(xs[q] - hi);                 \
        }                                                                     \
        _Pragma("unroll")                                                     \
        for (int q = 0; q < 4; q++) {                                         \
            float hi = tf32f(pb[q]);                                          \
            sBh_[bk * 72 + bn + q] = hi;                                      \
            sBl_[bk * 72 + bn + q] = tf32f(pb[q] - hi);                       \
        }                                                                     \
    }

    STORE_BUF(0, 0)
    __syncthreads();

    for (int kt = 0; kt < NKCH; kt++) {
        int k1 = (kt + 1) * 16;
        if (kt + 1 < NKCH) {
            float4 v0 = *(const float4*)&Arow[k1 + akb];
            float4 v1 = *(const float4*)&Arow[k1 + akb + 4];
            pa[0] = v0.x; pa[1] = v0.y; pa[2] = v0.z; pa[3] = v0.w;
            pa[4] = v1.x; pa[5] = v1.y; pa[6] = v1.z; pa[7] = v1.w;
            float4 vb = *(const float4*)&B[(size_t)(k1 + bk) * CQ + n0 + bn];
            pb[0] = vb.x; pb[1] = vb.y; pb[2] = vb.z; pb[3] = vb.w;
        }

        float* sAh = sm + (kt & 1) * GBUF;
        float* sAl = sAh + GSA;
        float* sBh = sAl + GSA;
        float* sBl = sBh + GSB;

#pragma unroll
        for (int ks = 0; ks < 2; ks++) {
            int kk = ks * 8;
            unsigned Ah[2][4], Al[2][4], Bh[4][2], Bl[4][2];
#pragma unroll
            for (int mt = 0; mt < 2; mt++) {
                int mb = wm * 32 + mt * 16 + g;
                Ah[mt][0] = su(sAh[(kk + t) * 136 + mb]);
                Ah[mt][1] = su(sAh[(kk + t) * 136 + mb + 8]);
                Ah[mt][2] = su(sAh[(kk + t + 4) * 136 + mb]);
                Ah[mt][3] = su(sAh[(kk + t + 4) * 136 + mb + 8]);
                Al[mt][0] = su(sAl[(kk + t) * 136 + mb]);
                Al[mt][1] = su(sAl[(kk + t) * 136 + mb + 8]);
                Al[mt][2] = su(sAl[(kk + t + 4) * 136 + mb]);
                Al[mt][3] = su(sAl[(kk + t + 4) * 136 + mb + 8]);
            }
#pragma unroll
            for (int nt = 0; nt < 4; nt++) {
                int nb = wn * 32 + nt * 8 + g;
                Bh[nt][0] = su(sBh[(kk + t) * 72 + nb]);
                Bh[nt][1] = su(sBh[(kk + t + 4) * 72 + nb]);
                Bl[nt][0] = su(sBl[(kk + t) * 72 + nb]);
                Bl[nt][1] = su(sBl[(kk + t + 4) * 72 + nb]);
            }
#pragma unroll
            for (int mt = 0; mt < 2; mt++)
#pragma unroll
                for (int nt = 0; nt < 4; nt++) {
                    MMA_TF32(c[mt][nt], Ah[mt], Bh[nt][0], Bh[nt][1]);
                    MMA_TF32(c[mt][nt], Ah[mt], Bl[nt][0], Bl[nt][1]);
                    MMA_TF32(c[mt][nt], Al[mt], Bh[nt][0], Bh[nt][1]);
                }
        }

        if (kt + 1 < NKCH) STORE_BUF((kt + 1) & 1, k1)
        __syncthreads();
    }
#undef STORE_BUF
}

// fused Q/K/V/Gate projections (LN applied to A on the fly)
__global__ void __launch_bounds__(256) qkvg_mma(const float* __restrict__ A,
                                                const float* __restrict__ gw,
                                                const float* __restrict__ bw,
                                                const float* __restrict__ wq,
                                                const float* __restrict__ wk,
                                                const float* __restrict__ wv,
                                                const float* __restrict__ wg,
                                                const float* __restrict__ bg,
                                                float qscale) {
    extern __shared__ float gsm[];
    int zi = blockIdx.z;
    const float* B = (zi == 0) ? wq : (zi == 1) ? wk : (zi == 2) ? wv : wg;
    float* O = (zi == 0) ? g_q : (zi == 1) ? g_k : (zi == 2) ? g_v : g_gate;

    float c[2][4][4] = {};
    gemm_core_db<1>(A, B, gw, bw, c, gsm);

    int lane = threadIdx.x & 31, w = threadIdx.x >> 5;
    int wm = w & 3, wn = w >> 2;
    int g = lane >> 2, t = lane & 3;
    int m0 = blockIdx.y * 128, n0 = blockIdx.x * 64;
#pragma unroll
    for (int mt = 0; mt < 2; mt++) {
        int r0 = m0 + wm * 32 + mt * 16 + g;
#pragma unroll
        for (int nt = 0; nt < 4; nt++) {
            int col = n0 + wn * 32 + nt * 8 + 2 * t;
            float v0 = c[mt][nt][0], v1 = c[mt][nt][1];
            float v2 = c[mt][nt][2], v3 = c[mt][nt][3];
            if (zi == 0) { v0 *= qscale; v1 *= qscale; v2 *= qscale; v3 *= qscale; }
            if (zi == 3) {
                float2 bb = *(const float2*)&bg[col];
                v0 = 1.f / (1.f + __expf(-(v0 + bb.x)));
                v1 = 1.f / (1.f + __expf(-(v1 + bb.y)));
                v2 = 1.f / (1.f + __expf(-(v2 + bb.x)));
                v3 = 1.f / (1.f + __expf(-(v3 + bb.y)));
            }
            *(float2*)&O[(size_t)r0 * CQ + col]       = make_float2(v0, v1);
            *(float2*)&O[(size_t)(r0 + 8) * CQ + col] = make_float2(v2, v3);
        }
    }
}

// out projection
__global__ void __launch_bounds__(256) out_mma(const float* __restrict__ A,
                                               const float* __restrict__ B,
                                               float* __restrict__ C,
                                               const float* __restrict__ bias) {
    extern __shared__ float gsm[];
    float c[2][4][4] = {};
    gemm_core_db<0>(A, B, (const float*)0, (const float*)0, c, gsm);

    int lane = threadIdx.x & 31, w = threadIdx.x >> 5;
    int wm = w & 3, wn = w >> 2;
    int g = lane >> 2, t = lane & 3;
    int m0 = blockIdx.y * 128, n0 = blockIdx.x * 64;
#pragma unroll
    for (int mt = 0; mt < 2; mt++) {
        int r0 = m0 + wm * 32 + mt * 16 + g;
#pragma unroll
        for (int nt = 0; nt < 4; nt++) {
            int col = n0 + wn * 32 + nt * 8 + 2 * t;
            float2 bb = *(const float2*)&bias[col];
            *(float2*)&C[(size_t)r0 * CQ + col] =
                make_float2(c[mt][nt][0] + bb.x, c[mt][nt][1] + bb.y);
            *(float2*)&C[(size_t)(r0 + 8) * CQ + col] =
                make_float2(c[mt][nt][2] + bb.x, c[mt][nt][3] + bb.y);
        }
    }
}

// ================= flash attention: 64 q-rows x 2 heads per block, 256 thr =================
// smem: Ks[2][64*68] | Vs[2][64*72] | Ps[8][16*68]; bias loaded direct to fragments
__global__ void __launch_bounds__(256) flash_mma() {
    extern __shared__ float fsm[];

    int tid = threadIdx.x, w = tid >> 5, lane = tid & 31;
    int hh = w >> 2, wl = w & 3;
    int g = lane >> 2, t = lane & 3;

    float* Ks = fsm + hh * 4352;
    float* Vs = fsm + 8704 + hh * 4608;
    float* Pw = fsm + 8704 + 9216 + w * 1088;

    int h  = blockIdx.y * 2 + hh;
    int i0 = blockIdx.x * 64;
    int irow = i0 + wl * 16 + g;

    unsigned aq[6][4];
    {
        const float* q0 = g_q + (size_t)irow * CQ + h * HD;
        const float* q8 = q0 + 8 * CQ;
#pragma unroll
        for (int ks = 0; ks < 6; ks++) {
            aq[ks][0] = f2tf(q0[ks * 8 + t]);
            aq[ks][1] = f2tf(q8[ks * 8 + t]);
            aq[ks][2] = f2tf(q0[ks * 8 + t + 4]);
            aq[ks][3] = f2tf(q8[ks * 8 + t + 4]);
        }
    }

    // bias row base pointers for this thread's fragment rows
    const float* scA = g_sc + ((size_t)irow * NH + h) * NTOK;
    const float* scB = scA + (size_t)8 * NH * NTOK;

    float o[6][4] = {};
    float mrunA = -1e30f, mrunB = -1e30f, lA = 0.f, lB = 0.f;

    for (int jt = 0; jt < 16; jt++) {
        int j0 = jt * 64;
        __syncthreads();

        // bias direct to fragments (gmem, overlaps with K/V smem fill below)
        float s[8][4];
#pragma unroll
        for (int nt = 0; nt < 8; nt++) {
            float2 bA = *(const float2*)&scA[j0 + nt * 8 + 2 * t];
            float2 bB = *(const float2*)&scB[j0 + nt * 8 + 2 * t];
            s[nt][0] = bA.x; s[nt][1] = bA.y; s[nt][2] = bB.x; s[nt][3] = bB.y;
        }

        // load K/V for both heads (tf32-rounded)
#pragma unroll
        for (int e = tid; e < 1536; e += 256) {
            int hd2 = (e >= 768);
            int e2 = e - hd2 * 768;
            int r = e2 / 12, cc = (e2 % 12) * 4;
            int hl = blockIdx.y * 2 + hd2;
            float* Kd = fsm + hd2 * 4352;
            float* Vd = fsm + 8704 + hd2 * 4608;
            float4 kv = *(const float4*)&g_k[(size_t)(j0 + r) * CQ + hl * HD + cc];
            Kd[r * 68 + cc + 0] = tf32f(kv.x); Kd[r * 68 + cc + 1] = tf32f(kv.y);
            Kd[r * 68 + cc + 2] = tf32f(kv.z); Kd[r * 68 + cc + 3] = tf32f(kv.w);
            float4 vv = *(const float4*)&g_v[(size_t)(j0 + r) * CQ + hl * HD + cc];
            Vd[r * 72 + cc + 0] = tf32f(vv.x); Vd[r * 72 + cc + 1] = tf32f(vv.y);
            Vd[r * 72 + cc + 2] = tf32f(vv.z); Vd[r * 72 + cc + 3] = tf32f(vv.w);
        }
        __syncthreads();

#pragma unroll
        for (int ks = 0; ks < 6; ks++) {
#pragma unroll
            for (int nt = 0; nt < 8; nt++) {
                unsigned b0 = su(Ks[(nt * 8 + g) * 68 + ks * 8 + t]);
                unsigned b1 = su(Ks[(nt * 8 + g) * 68 + ks * 8 + t + 4]);
                MMA_TF32(s[nt], aq[ks], b0, b1);
            }
        }

        float mA = -1e30f, mB = -1e30f;
#pragma unroll
        for (int nt = 0; nt < 8; nt++) {
            mA = fmaxf(mA, fmaxf(s[nt][0], s[nt][1]));
            mB = fmaxf(mB, fmaxf(s[nt][2], s[nt][3]));
        }
#pragma unroll
        for (int oo = 1; oo <= 2; oo <<= 1) {
            mA = fmaxf(mA, __shfl_xor_sync(0xffffffffu, mA, oo));
            mB = fmaxf(mB, __shfl_xor_sync(0xffffffffu, mB, oo));
        }
        float mnA = fmaxf(mrunA, mA), mnB = fmaxf(mrunB, mB);
        float alA = __expf(mrunA - mnA), alB = __expf(mrunB - mnB);
        mrunA = mnA; mrunB = mnB;

        float sumA = 0.f, sumB = 0.f;
#pragma unroll
        for (int nt = 0; nt < 8; nt++) {
            s[nt][0] = __expf(s[nt][0] - mnA); s[nt][1] = __expf(s[nt][1] - mnA);
            s[nt][2] = __expf(s[nt][2] - mnB); s[nt][3] = __expf(s[nt][3] - mnB);
            sumA += s[nt][0] + s[nt][1];
            sumB += s[nt][2] + s[nt][3];
        }
#pragma unroll
        for (int oo = 1; oo <= 2; oo <<= 1) {
            sumA += __shfl_xor_sync(0xffffffffu, sumA, oo);
            sumB += __shfl_xor_sync(0xffffffffu, sumB, oo);
        }
        lA = lA * alA + sumA;
        lB = lB * alB + sumB;
#pragma unroll
        for (int nd = 0; nd < 6; nd++) {
            o[nd][0] *= alA; o[nd][1] *= alA;
            o[nd][2] *= alB; o[nd][3] *= alB;
        }

#pragma unroll
        for (int nt = 0; nt < 8; nt++) {
            *(float2*)&Pw[g * 68 + nt * 8 + 2 * t]       = make_float2(tf32f(s[nt][0]), tf32f(s[nt][1]));
            *(float2*)&Pw[(g + 8) * 68 + nt * 8 + 2 * t] = make_float2(tf32f(s[nt][2]), tf32f(s[nt][3]));
        }
        __syncwarp();

#pragma unroll
        for (int ks = 0; ks < 8; ks++) {
            unsigned pa[4];
            pa[0] = su(Pw[g * 68 + ks * 8 + t]);
            pa[1] = su(Pw[(g + 8) * 68 + ks * 8 + t]);
            pa[2] = su(Pw[g * 68 + ks * 8 + t + 4]);
            pa[3] = su(Pw[(g + 8) * 68 + ks * 8 + t + 4]);
#pragma unroll
            for (int nd = 0; nd < 6; nd++) {
                unsigned b0 = su(Vs[(ks * 8 + t) * 72 + nd * 8 + g]);
                unsigned b1 = su(Vs[(ks * 8 + t + 4) * 72 + nd * 8 + g]);
                MMA_TF32(o[nd], pa, b0, b1);
            }
        }
    }

    float iA = 1.f / lA, iB = 1.f / lB;
#pragma unroll
    for (int nd = 0; nd < 6; nd++) {
        int col = h * HD + nd * 8 + 2 * t;
        size_t iAx = (size_t)irow * CQ + col;
        size_t iBx = (size_t)(irow + 8) * CQ + col;
        float2 ga = *(const float2*)&g_gate[iAx];
        float2 gb = *(const float2*)&g_gate[iBx];
        *(float2*)&g_og[iAx] = make_float2(o[nd][0] * iA * ga.x, o[nd][1] * iA * ga.y);
        *(float2*)&g_og[iBx] = make_float2(o[nd][2] * iB * gb.x, o[nd][3] * iB * gb.y);
    }
}

// ------------------------------- launch -------------------------------
#define PB_SMEM ((128 * 132 + 16 * 132 + 16 * 132 + 256) * 4)
#define FL_SMEM ((2 * 4352 + 2 * 4608 + 8 * 1088) * 4)

extern "C" void kernel_launch(void* const* d_in, const int* in_sizes, int n_in,
                              void* d_out, int out_size) {
    const float* a    = (const float*)d_in[0];
    const float* z    = (const float*)d_in[1];
    const float* mask = (const float*)d_in[2];
    const float* ga   = (const float*)d_in[3];
    const float* ba   = (const float*)d_in[4];
    const float* gz   = (const float*)d_in[5];
    const float* bz   = (const float*)d_in[6];
    const float* wz   = (const float*)d_in[7];
    const float* wq   = (const float*)d_in[8];
    const float* wk   = (const float*)d_in[9];
    const float* wv   = (const float*)d_in[10];
    const float* wg   = (const float*)d_in[11];
    const float* bg   = (const float*)d_in[12];
    const float* wo   = (const float*)d_in[13];
    const float* bo   = (const float*)d_in[14];
    float* out = (float*)d_out;

    float *p_og;
    cudaGetSymbolAddress((void**)&p_og, g_og);

    static int init_done = 0;
    if (!init_done) {
        cudaFuncSetAttribute(flash_mma, cudaFuncAttributeMaxDynamicSharedMemorySize, FL_SMEM);
        cudaFuncSetAttribute(pair_mma,  cudaFuncAttributeMaxDynamicSharedMemorySize, PB_SMEM);
        cudaFuncSetAttribute(qkvg_mma,  cudaFuncAttributeMaxDynamicSharedMemorySize, GEMM_DB_SMEM);
        cudaFuncSetAttribute(out_mma,   cudaFuncAttributeMaxDynamicSharedMemorySize, GEMM_DB_SMEM);
        init_done = 1;
    }

    a_stats_kernel<<<NTOK, 256>>>(a);
    prep_kernel<<<1, 128>>>(gz, bz, wz);
    pair_mma<<<dim3(NTOK / 128, NTOK), 256, PB_SMEM>>>(z, mask);

    float qscale = 1.0f / sqrtf((float)HD);
    qkvg_mma<<<dim3(CQ / 64, NTOK / 128, 4), 256, GEMM_DB_SMEM>>>(a, ga, ba, wq, wk, wv, wg, bg, qscale);

    flash_mma<<<dim3(NTOK / 64, NH / 2), 256, FL_SMEM>>>();

    out_mma<<<dim3(CQ / 64, NTOK / 128), 256, GEMM_DB_SMEM>>>(p_og, wo, out, bo);
}

// round 12
// speedup vs baseline: 1.6449x; 1.0830x over previous
#include <cuda_runtime.h>
#include <cuda_bf16.h>
#include <math.h>

#define NTOK 1024
#define CQ   768
#define CZ   128
#define NH   16
#define HD   48

// ---------------- scratch (static device memory) ----------------
__device__ float g_q   [NTOK * CQ];
__device__ float g_k   [NTOK * CQ];
__device__ float g_v   [NTOK * CQ];
__device__ float g_gate[NTOK * CQ];
__device__ float g_og  [NTOK * CQ];
__device__ float g_sc  [(size_t)NTOK * NH * NTOK];   // pair+mask bias, layout [i][h][j]
__device__ float g_wp  [CZ * NH];
__device__ float g_wpT [NH * 132];
__device__ float g_Wh  [NH];
__device__ float g_ch  [NH];
__device__ float g_mu  [NTOK];
__device__ float g_rs  [NTOK];

// ---------------- helpers ----------------
__device__ __forceinline__ unsigned f2tf(float x) {
    unsigned u; asm("cvt.rna.tf32.f32 %0, %1;" : "=r"(u) : "f"(x)); return u;
}
__device__ __forceinline__ float tf32f(float x) { return __uint_as_float(f2tf(x)); }
__device__ __forceinline__ unsigned su(float x) { return __float_as_uint(x); }

// pack (even k -> low half, odd k -> high half), hi/lo bf16 split
__device__ __forceinline__ void bfsplit2(float e, float o, unsigned& hw, unsigned& lw) {
    __nv_bfloat162 h2, l2;
    h2.x = __float2bfloat16_rn(e);
    h2.y = __float2bfloat16_rn(o);
    l2.x = __float2bfloat16_rn(e - __bfloat162float(h2.x));
    l2.y = __float2bfloat16_rn(o - __bfloat162float(h2.y));
    hw = *(unsigned*)&h2;
    lw = *(unsigned*)&l2;
}

#define MMA_TF32(c, a, b0_, b1_)                                              \
    asm volatile("mma.sync.aligned.m16n8k8.row.col.f32.tf32.tf32.f32 "        \
                 "{%0,%1,%2,%3}, {%4,%5,%6,%7}, {%8,%9}, {%0,%1,%2,%3};"      \
                 : "+f"(c[0]), "+f"(c[1]), "+f"(c[2]), "+f"(c[3])             \
                 : "r"(a[0]), "r"(a[1]), "r"(a[2]), "r"(a[3]),                \
                   "r"(b0_), "r"(b1_));

#define MMA_BF16(c, a, b0_, b1_)                                              \
    asm volatile("mma.sync.aligned.m16n8k16.row.col.f32.bf16.bf16.f32 "       \
                 "{%0,%1,%2,%3}, {%4,%5,%6,%7}, {%8,%9}, {%0,%1,%2,%3};"      \
                 : "+f"(c[0]), "+f"(c[1]), "+f"(c[2]), "+f"(c[3])             \
                 : "r"(a[0]), "r"(a[1]), "r"(a[2]), "r"(a[3]),                \
                   "r"(b0_), "r"(b1_));

// ---------------- per-row LN stats of a ----------------
__global__ void __launch_bounds__(256) a_stats_kernel(const float* __restrict__ a) {
    int row = blockIdx.x;
    int tid = threadIdx.x;
    const float* x = a + (size_t)row * CQ;
    __shared__ float red[256];

    float xv[3];
    float s = 0.f;
#pragma unroll
    for (int k = 0; k < 3; k++) { xv[k] = x[tid + k * 256]; s += xv[k]; }
    red[tid] = s; __syncthreads();
    for (int st = 128; st > 0; st >>= 1) { if (tid < st) red[tid] += red[tid + st]; __syncthreads(); }
    float mu = red[0] * (1.f / CQ);
    __syncthreads();

    float s2 = 0.f;
#pragma unroll
    for (int k = 0; k < 3; k++) { float d = xv[k] - mu; s2 += d * d; }
    red[tid] = s2; __syncthreads();
    for (int st = 128; st > 0; st >>= 1) { if (tid < st) red[tid] += red[tid + st]; __syncthreads(); }
    if (tid == 0) {
        g_mu[row] = mu;
        g_rs[row] = rsqrtf(red[0] * (1.f / CQ) + 1e-5f);
    }
}

// ---------------- pair-bias precompute ----------------
__global__ void prep_kernel(const float* __restrict__ gz,
                            const float* __restrict__ bz,
                            const float* __restrict__ wz) {
    int tid = threadIdx.x;       // 128
    float gzc = gz[tid];
    for (int h = 0; h < NH; h++) {
        float w = gzc * wz[tid * NH + h];
        g_wp[tid * NH + h] = w;
        g_wpT[h * 132 + tid] = tf32f(w);
    }
    __syncthreads();
    if (tid < NH) {
        float W = 0.f, C = 0.f;
        for (int c = 0; c < CZ; c++) {
            W += g_wp[c * NH + tid];
            C += bz[c] * wz[c * NH + tid];
        }
        g_Wh[tid] = W;
        g_ch[tid] = C;
    }
}

// ---------------- pair bias via tensor cores (unchanged, proven) ----------------
__global__ void __launch_bounds__(256) pair_mma(const float* __restrict__ z,
                                                const float* __restrict__ mask) {
    extern __shared__ float psm[];
    float* zs  = psm;                     // 128*132
    float* wpt = zs + 128 * 132;          // 16*132
    float* sb  = wpt + 16 * 132;          // 16*132
    float* mus = sb + 16 * 132;           // 128
    float* rss = mus + 128;               // 128

    int i  = blockIdx.y;
    int j0 = blockIdx.x * 128;
    int tid = threadIdx.x, lane = tid & 31, w = tid >> 5;
    int g = lane >> 2, t = lane & 3;

    for (int e = tid; e < NH * 132; e += 256) wpt[e] = g_wpT[e];

    int row = tid >> 1, c0 = (tid & 1) * 64;
    const float* zrow = z + ((size_t)i * NTOK + j0 + row) * CZ + c0;
    float s1 = 0.f, s2 = 0.f;
#pragma unroll
    for (int q = 0; q < 16; q++) {
        float4 v = *(const float4*)&zrow[q * 4];
        s1 += v.x + v.y + v.z + v.w;
        s2 += v.x * v.x + v.y * v.y + v.z * v.z + v.w * v.w;
        float4 hv = make_float4(tf32f(v.x), tf32f(v.y), tf32f(v.z), tf32f(v.w));
        *(float4*)&zs[row * 132 + c0 + q * 4] = hv;
    }
    s1 += __shfl_xor_sync(0xffffffffu, s1, 1);
    s2 += __shfl_xor_sync(0xffffffffu, s2, 1);
    float mu = s1 * (1.f / CZ);
    float var = s2 * (1.f / CZ) - mu * mu;
    float rs = rsqrtf(var + 1e-5f);
    if ((tid & 1) == 0) { mus[row] = mu; rss[row] = rs; }
    __syncthreads();

    int wr = w * 16;
    float c[2][4] = {};
#pragma unroll
    for (int ks = 0; ks < 16; ks++) {
        int kk = ks * 8;
        unsigned a[4];
        a[0] = su(zs[(wr + g) * 132 + kk + t]);
        a[1] = su(zs[(wr + g + 8) * 132 + kk + t]);
        a[2] = su(zs[(wr + g) * 132 + kk + t + 4]);
        a[3] = su(zs[(wr + g + 8) * 132 + kk + t + 4]);
#pragma unroll
        for (int nt = 0; nt < 2; nt++) {
            unsigned b0 = su(wpt[(nt * 8 + g) * 132 + kk + t]);
            unsigned b1 = su(wpt[(nt * 8 + g) * 132 + kk + t + 4]);
            MMA_TF32(c[nt], a, b0, b1);
        }
    }

    float muA = mus[wr + g], rsA = rss[wr + g];
    float muB = mus[wr + g + 8], rsB = rss[wr + g + 8];
#pragma unroll
    for (int nt = 0; nt < 2; nt++) {
#pragma unroll
        for (int cc = 0; cc < 2; cc++) {
            int h = nt * 8 + 2 * t + cc;
            float W = g_Wh[h], C0 = g_ch[h];
            sb[h * 132 + wr + g]     = rsA * (c[nt][cc]     - muA * W) + C0;
            sb[h * 132 + wr + g + 8] = rsB * (c[nt][cc + 2] - muB * W) + C0;
        }
    }
    __syncthreads();

    float mi = mask[i];
#pragma unroll
    for (int e = tid; e < NH * 128; e += 256) {
        int h = e >> 7, j = e & 127;
        float mb = 1.0e9f * (mi * mask[j0 + j] - 1.f);
        g_sc[((size_t)i * NH + h) * NTOK + j0 + j] = sb[h * 132 + j] + mb;
    }
}

// ================= 3xBF16-split GEMM, 128x64 tile, BK=16 (1 mma k-step/chunk) =================
// packed bf16x2 smem: sAh/sAl [8][136] words, sBh/sBl [8][72] words
template <int LN_A>
__device__ __forceinline__ void gemm_core_bf(const float* __restrict__ A,
                                             const float* __restrict__ B,
                                             const float* __restrict__ gw,
                                             const float* __restrict__ bw,
                                             float c[2][4][4],
                                             unsigned* sAh, unsigned* sAl,
                                             unsigned* sBh, unsigned* sBl) {
    int tid  = threadIdx.x;
    int lane = tid & 31, w = tid >> 5;
    int wm = w & 3, wn = w >> 2;
    int g = lane >> 2, t = lane & 3;
    int m0 = blockIdx.y * 128, n0 = blockIdx.x * 64;
    int arow = tid >> 1, akb = (tid & 1) * 8;
    int bp = tid >> 5, bn = lane * 2;    // k-pair 0..7, n 0..62 step 2

    float mu = 0.f, rs = 1.f;
    if (LN_A) { mu = g_mu[m0 + arow]; rs = g_rs[m0 + arow]; }
    const float* Arow = A + (size_t)(m0 + arow) * CQ;

    for (int k0 = 0; k0 < CQ; k0 += 16) {
        __syncthreads();
        // ---- A tile: 8 consecutive k per thread -> 4 packed words (hi,lo) ----
        {
            float4 v0 = *(const float4*)&Arow[k0 + akb];
            float4 v1 = *(const float4*)&Arow[k0 + akb + 4];
            float xs[8] = {v0.x, v0.y, v0.z, v0.w, v1.x, v1.y, v1.z, v1.w};
            if (LN_A) {
#pragma unroll
                for (int q = 0; q < 8; q++)
                    xs[q] = (xs[q] - mu) * rs * gw[k0 + akb + q] + bw[k0 + akb + q];
            }
#pragma unroll
            for (int q = 0; q < 4; q++) {
                unsigned hw, lw;
                bfsplit2(xs[2 * q], xs[2 * q + 1], hw, lw);
                int p = (akb >> 1) + q;
                sAh[p * 136 + arow] = hw;
                sAl[p * 136 + arow] = lw;
            }
        }
        // ---- B tile: thread loads 2 n for 2 consecutive k rows ----
        {
            const float* Bp = &B[(size_t)(k0 + 2 * bp) * CQ + n0 + bn];
            float2 r0 = *(const float2*)Bp;
            float2 r1 = *(const float2*)(Bp + CQ);
            unsigned hw0, lw0, hw1, lw1;
            bfsplit2(r0.x, r1.x, hw0, lw0);
            bfsplit2(r0.y, r1.y, hw1, lw1);
            *(uint2*)&sBh[bp * 72 + bn] = make_uint2(hw0, hw1);
            *(uint2*)&sBl[bp * 72 + bn] = make_uint2(lw0, lw1);
        }
        __syncthreads();

        // ---- fragments + mma: ONE m16n8k16 step covers the 16-k chunk ----
        unsigned Ah[2][4], Al[2][4], Bh[4][2], Bl[4][2];
#pragma unroll
        for (int mt = 0; mt < 2; mt++) {
            int mb = wm * 32 + mt * 16 + g;
            Ah[mt][0] = sAh[t * 136 + mb];
            Ah[mt][1] = sAh[t * 136 + mb + 8];
            Ah[mt][2] = sAh[(t + 4) * 136 + mb];
            Ah[mt][3] = sAh[(t + 4) * 136 + mb + 8];
            Al[mt][0] = sAl[t * 136 + mb];
            Al[mt][1] = sAl[t * 136 + mb + 8];
            Al[mt][2] = sAl[(t + 4) * 136 + mb];
            Al[mt][3] = sAl[(t + 4) * 136 + mb + 8];
        }
#pragma unroll
        for (int nt = 0; nt < 4; nt++) {
            int nb = wn * 32 + nt * 8 + g;
            Bh[nt][0] = sBh[t * 72 + nb];
            Bh[nt][1] = sBh[(t + 4) * 72 + nb];
            Bl[nt][0] = sBl[t * 72 + nb];
            Bl[nt][1] = sBl[(t + 4) * 72 + nb];
        }
#pragma unroll
        for (int mt = 0; mt < 2; mt++)
#pragma unroll
            for (int nt = 0; nt < 4; nt++) {
                MMA_BF16(c[mt][nt], Ah[mt], Bh[nt][0], Bh[nt][1]);
                MMA_BF16(c[mt][nt], Ah[mt], Bl[nt][0], Bl[nt][1]);
                MMA_BF16(c[mt][nt], Al[mt], Bh[nt][0], Bh[nt][1]);
            }
    }
}

#define GEMM_BF_SMEM                                                          \
    __shared__ unsigned sAh[8 * 136], sAl[8 * 136];                           \
    __shared__ unsigned sBh[8 * 72],  sBl[8 * 72];

// fused Q/K/V/Gate projections (LN applied to A on the fly)
__global__ void __launch_bounds__(256) qkvg_mma(const float* __restrict__ A,
                                                const float* __restrict__ gw,
                                                const float* __restrict__ bw,
                                                const float* __restrict__ wq,
                                                const float* __restrict__ wk,
                                                const float* __restrict__ wv,
                                                const float* __restrict__ wg,
                                                const float* __restrict__ bg,
                                                float qscale) {
    GEMM_BF_SMEM
    int zi = blockIdx.z;
    const float* B = (zi == 0) ? wq : (zi == 1) ? wk : (zi == 2) ? wv : wg;
    float* O = (zi == 0) ? g_q : (zi == 1) ? g_k : (zi == 2) ? g_v : g_gate;

    float c[2][4][4] = {};
    gemm_core_bf<1>(A, B, gw, bw, c, sAh, sAl, sBh, sBl);

    int lane = threadIdx.x & 31, w = threadIdx.x >> 5;
    int wm = w & 3, wn = w >> 2;
    int g = lane >> 2, t = lane & 3;
    int m0 = blockIdx.y * 128, n0 = blockIdx.x * 64;
#pragma unroll
    for (int mt = 0; mt < 2; mt++) {
        int r0 = m0 + wm * 32 + mt * 16 + g;
#pragma unroll
        for (int nt = 0; nt < 4; nt++) {
            int col = n0 + wn * 32 + nt * 8 + 2 * t;
            float v0 = c[mt][nt][0], v1 = c[mt][nt][1];
            float v2 = c[mt][nt][2], v3 = c[mt][nt][3];
            if (zi == 0) { v0 *= qscale; v1 *= qscale; v2 *= qscale; v3 *= qscale; }
            if (zi == 3) {
                float2 bb = *(const float2*)&bg[col];
                v0 = 1.f / (1.f + __expf(-(v0 + bb.x)));
                v1 = 1.f / (1.f + __expf(-(v1 + bb.y)));
                v2 = 1.f / (1.f + __expf(-(v2 + bb.x)));
                v3 = 1.f / (1.f + __expf(-(v3 + bb.y)));
            }
            *(float2*)&O[(size_t)r0 * CQ + col]       = make_float2(v0, v1);
            *(float2*)&O[(size_t)(r0 + 8) * CQ + col] = make_float2(v2, v3);
        }
    }
}

// out projection
__global__ void __launch_bounds__(256) out_mma(const float* __restrict__ A,
                                               const float* __restrict__ B,
                                               float* __restrict__ C,
                                               const float* __restrict__ bias) {
    GEMM_BF_SMEM
    float c[2][4][4] = {};
    gemm_core_bf<0>(A, B, (const float*)0, (const float*)0, c, sAh, sAl, sBh, sBl);

    int lane = threadIdx.x & 31, w = threadIdx.x >> 5;
    int wm = w & 3, wn = w >> 2;
    int g = lane >> 2, t = lane & 3;
    int m0 = blockIdx.y * 128, n0 = blockIdx.x * 64;
#pragma unroll
    for (int mt = 0; mt < 2; mt++) {
        int r0 = m0 + wm * 32 + mt * 16 + g;
#pragma unroll
        for (int nt = 0; nt < 4; nt++) {
            int col = n0 + wn * 32 + nt * 8 + 2 * t;
            float2 bb = *(const float2*)&bias[col];
            *(float2*)&C[(size_t)r0 * CQ + col] =
                make_float2(c[mt][nt][0] + bb.x, c[mt][nt][1] + bb.y);
            *(float2*)&C[(size_t)(r0 + 8) * CQ + col] =
                make_float2(c[mt][nt][2] + bb.x, c[mt][nt][3] + bb.y);
        }
    }
}

// ================= flash attention: 64 q-rows x 2 heads per block, 256 thr =================
// smem: Ks[2][64*68] | Vs[2][64*72] | Ps[8][16*68]; bias loaded direct to fragments
__global__ void __launch_bounds__(256) flash_mma() {
    extern __shared__ float fsm[];

    int tid = threadIdx.x, w = tid >> 5, lane = tid & 31;
    int hh = w >> 2, wl = w & 3;
    int g = lane >> 2, t = lane & 3;

    float* Ks = fsm + hh * 4352;
    float* Vs = fsm + 8704 + hh * 4608;
    float* Pw = fsm + 8704 + 9216 + w * 1088;

    int h  = blockIdx.y * 2 + hh;
    int i0 = blockIdx.x * 64;
    int irow = i0 + wl * 16 + g;

    unsigned aq[6][4];
    {
        const float* q0 = g_q + (size_t)irow * CQ + h * HD;
        const float* q8 = q0 + 8 * CQ;
#pragma unroll
        for (int ks = 0; ks < 6; ks++) {
            aq[ks][0] = f2tf(q0[ks * 8 + t]);
            aq[ks][1] = f2tf(q8[ks * 8 + t]);
            aq[ks][2] = f2tf(q0[ks * 8 + t + 4]);
            aq[ks][3] = f2tf(q8[ks * 8 + t + 4]);
        }
    }

    const float* scA = g_sc + ((size_t)irow * NH + h) * NTOK;
    const float* scB = scA + (size_t)8 * NH * NTOK;

    float o[6][4] = {};
    float mrunA = -1e30f, mrunB = -1e30f, lA = 0.f, lB = 0.f;

    for (int jt = 0; jt < 16; jt++) {
        int j0 = jt * 64;
        __syncthreads();

        float s[8][4];
#pragma unroll
        for (int nt = 0; nt < 8; nt++) {
            float2 bA = *(const float2*)&scA[j0 + nt * 8 + 2 * t];
            float2 bB = *(const float2*)&scB[j0 + nt * 8 + 2 * t];
            s[nt][0] = bA.x; s[nt][1] = bA.y; s[nt][2] = bB.x; s[nt][3] = bB.y;
        }

#pragma unroll
        for (int e = tid; e < 1536; e += 256) {
            int hd2 = (e >= 768);
            int e2 = e - hd2 * 768;
            int r = e2 / 12, cc = (e2 % 12) * 4;
            int hl = blockIdx.y * 2 + hd2;
            float* Kd = fsm + hd2 * 4352;
            float* Vd = fsm + 8704 + hd2 * 4608;
            float4 kv = *(const float4*)&g_k[(size_t)(j0 + r) * CQ + hl * HD + cc];
            Kd[r * 68 + cc + 0] = tf32f(kv.x); Kd[r * 68 + cc + 1] = tf32f(kv.y);
            Kd[r * 68 + cc + 2] = tf32f(kv.z); Kd[r * 68 + cc + 3] = tf32f(kv.w);
            float4 vv = *(const float4*)&g_v[(size_t)(j0 + r) * CQ + hl * HD + cc];
            Vd[r * 72 + cc + 0] = tf32f(vv.x); Vd[r * 72 + cc + 1] = tf32f(vv.y);
            Vd[r * 72 + cc + 2] = tf32f(vv.z); Vd[r * 72 + cc + 3] = tf32f(vv.w);
        }
        __syncthreads();

#pragma unroll
        for (int ks = 0; ks < 6; ks++) {
#pragma unroll
            for (int nt = 0; nt < 8; nt++) {
                unsigned b0 = su(Ks[(nt * 8 + g) * 68 + ks * 8 + t]);
                unsigned b1 = su(Ks[(nt * 8 + g) * 68 + ks * 8 + t + 4]);
                MMA_TF32(s[nt], aq[ks], b0, b1);
            }
        }

        float mA = -1e30f, mB = -1e30f;
#pragma unroll
        for (int nt = 0; nt < 8; nt++) {
            mA = fmaxf(mA, fmaxf(s[nt][0], s[nt][1]));
            mB = fmaxf(mB, fmaxf(s[nt][2], s[nt][3]));
        }
#pragma unroll
        for (int oo = 1; oo <= 2; oo <<= 1) {
            mA = fmaxf(mA, __shfl_xor_sync(0xffffffffu, mA, oo));
            mB = fmaxf(mB, __shfl_xor_sync(0xffffffffu, mB, oo));
        }
        float mnA = fmaxf(mrunA, mA), mnB = fmaxf(mrunB, mB);
        float alA = __expf(mrunA - mnA), alB = __expf(mrunB - mnB);
        mrunA = mnA; mrunB = mnB;

        float sumA = 0.f, sumB = 0.f;
#pragma unroll
        for (int nt = 0; nt < 8; nt++) {
            s[nt][0] = __expf(s[nt][0] - mnA); s[nt][1] = __expf(s[nt][1] - mnA);
            s[nt][2] = __expf(s[nt][2] - mnB); s[nt][3] = __expf(s[nt][3] - mnB);
            sumA += s[nt][0] + s[nt][1];
            sumB += s[nt][2] + s[nt][3];
        }
#pragma unroll
        for (int oo = 1; oo <= 2; oo <<= 1) {
            sumA += __shfl_xor_sync(0xffffffffu, sumA, oo);
            sumB += __shfl_xor_sync(0xffffffffu, sumB, oo);
        }
        lA = lA * alA + sumA;
        lB = lB * alB + sumB;
#pragma unroll
        for (int nd = 0; nd < 6; nd++) {
            o[nd][0] *= alA; o[nd][1] *= alA;
            o[nd][2] *= alB; o[nd][3] *= alB;
        }

#pragma unroll
        for (int nt = 0; nt < 8; nt++) {
            *(float2*)&Pw[g * 68 + nt * 8 + 2 * t]       = make_float2(tf32f(s[nt][0]), tf32f(s[nt][1]));
            *(float2*)&Pw[(g + 8) * 68 + nt * 8 + 2 * t] = make_float2(tf32f(s[nt][2]), tf32f(s[nt][3]));
        }
        __syncwarp();

#pragma unroll
        for (int ks = 0; ks < 8; ks++) {
            unsigned pa[4];
            pa[0] = su(Pw[g * 68 + ks * 8 + t]);
            pa[1] = su(Pw[(g + 8) * 68 + ks * 8 + t]);
            pa[2] = su(Pw[g * 68 + ks * 8 + t + 4]);
            pa[3] = su(Pw[(g + 8) * 68 + ks * 8 + t + 4]);
#pragma unroll
            for (int nd = 0; nd < 6; nd++) {
                unsigned b0 = su(Vs[(ks * 8 + t) * 72 + nd * 8 + g]);
                unsigned b1 = su(Vs[(ks * 8 + t + 4) * 72 + nd * 8 + g]);
                MMA_TF32(o[nd], pa, b0, b1);
            }
        }
    }

    float iA = 1.f / lA, iB = 1.f / lB;
#pragma unroll
    for (int nd = 0; nd < 6; nd++) {
        int col = h * HD + nd * 8 + 2 * t;
        size_t iAx = (size_t)irow * CQ + col;
        size_t iBx = (size_t)(irow + 8) * CQ + col;
        float2 ga = *(const float2*)&g_gate[iAx];
        float2 gb = *(const float2*)&g_gate[iBx];
        *(float2*)&g_og[iAx] = make_float2(o[nd][0] * iA * ga.x, o[nd][1] * iA * ga.y);
        *(float2*)&g_og[iBx] = make_float2(o[nd][2] * iB * gb.x, o[nd][3] * iB * gb.y);
    }
}

// ------------------------------- launch -------------------------------
#define PB_SMEM ((128 * 132 + 16 * 132 + 16 * 132 + 256) * 4)
#define FL_SMEM ((2 * 4352 + 2 * 4608 + 8 * 1088) * 4)

extern "C" void kernel_launch(void* const* d_in, const int* in_sizes, int n_in,
                              void* d_out, int out_size) {
    const float* a    = (const float*)d_in[0];
    const float* z    = (const float*)d_in[1];
    const float* mask = (const float*)d_in[2];
    const float* ga   = (const float*)d_in[3];
    const float* ba   = (const float*)d_in[4];
    const float* gz   = (const float*)d_in[5];
    const float* bz   = (const float*)d_in[6];
    const float* wz   = (const float*)d_in[7];
    const float* wq   = (const float*)d_in[8];
    const float* wk   = (const float*)d_in[9];
    const float* wv   = (const float*)d_in[10];
    const float* wg   = (const float*)d_in[11];
    const float* bg   = (const float*)d_in[12];
    const float* wo   = (const float*)d_in[13];
    const float* bo   = (const float*)d_in[14];
    float* out = (float*)d_out;

    float *p_og;
    cudaGetSymbolAddress((void**)&p_og, g_og);

    static int init_done = 0;
    if (!init_done) {
        cudaFuncSetAttribute(flash_mma, cudaFuncAttributeMaxDynamicSharedMemorySize, FL_SMEM);
        cudaFuncSetAttribute(pair_mma,  cudaFuncAttributeMaxDynamicSharedMemorySize, PB_SMEM);
        init_done = 1;
    }

    a_stats_kernel<<<NTOK, 256>>>(a);
    prep_kernel<<<1, 128>>>(gz, bz, wz);
    pair_mma<<<dim3(NTOK / 128, NTOK), 256, PB_SMEM>>>(z, mask);

    float qscale = 1.0f / sqrtf((float)HD);
    qkvg_mma<<<dim3(CQ / 64, NTOK / 128, 4), 256>>>(a, ga, ba, wq, wk, wv, wg, bg, qscale);

    flash_mma<<<dim3(NTOK / 64, NH / 2), 256, FL_SMEM>>>();

    out_mma<<<dim3(CQ / 64, NTOK / 128), 256>>>(p_og, wo, out, bo);
}